// round 5
// baseline (speedup 1.0000x reference)
#include <cuda_runtime.h>
#include <cuda_bf16.h>
#include <math.h>
#include <stdint.h>

// Problem constants (B=2, S=2048, D=1024, H=16, DPH=64)
#define BATCH 2
#define SEQ   2048
#define DIM   1024
#define HEADS 16
#define DPH   64
#define MROWS (BATCH * SEQ)   // 4096

typedef unsigned long long u64;

// ---------------------------------------------------------------------------
// Scratch (allocation-free rule: __device__ globals)
// ---------------------------------------------------------------------------
__device__ float g_q[BATCH * SEQ * DIM];
__device__ float g_k[BATCH * SEQ * DIM];
__device__ float g_v[BATCH * SEQ * DIM];
__device__ float g_ctx[BATCH * SEQ * DIM];
__device__ __nv_bfloat16 g_ah[MROWS * DIM];    // activation hi
__device__ __nv_bfloat16 g_al[MROWS * DIM];    // activation lo
__device__ __nv_bfloat16 g_wh[DIM * DIM];      // W^T hi  [n][k]
__device__ __nv_bfloat16 g_wl[DIM * DIM];      // W^T lo  [n][k]

// ---------------------------------------------------------------------------
// Baseline-ISA PTX helpers (no sm_103a-only features!)
// ---------------------------------------------------------------------------
__device__ __forceinline__ void cpasync16(uint32_t dst, const void* src) {
    asm volatile("cp.async.cg.shared.global [%0], [%1], 16;"
                 :: "r"(dst), "l"(src) : "memory");
}
__device__ __forceinline__ void ldsm4(uint32_t* r, uint32_t addr) {
    asm volatile("ldmatrix.sync.aligned.m8n8.x4.shared.b16 {%0,%1,%2,%3}, [%4];"
                 : "=r"(r[0]), "=r"(r[1]), "=r"(r[2]), "=r"(r[3]) : "r"(addr));
}
__device__ __forceinline__ void mma_bf16(float* c, const uint32_t* a, const uint32_t* b) {
    asm volatile("mma.sync.aligned.m16n8k16.row.col.f32.bf16.bf16.f32 "
                 "{%0,%1,%2,%3}, {%4,%5,%6,%7}, {%8,%9}, {%0,%1,%2,%3};"
                 : "+f"(c[0]), "+f"(c[1]), "+f"(c[2]), "+f"(c[3])
                 : "r"(a[0]), "r"(a[1]), "r"(a[2]), "r"(a[3]),
                   "r"(b[0]), "r"(b[1]));
}
// packed f32x2 (sm_100+ baseline)
__device__ __forceinline__ u64 ffma2(u64 a, u64 b, u64 c) {
    u64 d;
    asm("fma.rn.f32x2 %0, %1, %2, %3;" : "=l"(d) : "l"(a), "l"(b), "l"(c));
    return d;
}
__device__ __forceinline__ u64 fmul2(u64 a, u64 b) {
    u64 d;
    asm("mul.rn.f32x2 %0, %1, %2;" : "=l"(d) : "l"(a), "l"(b));
    return d;
}
__device__ __forceinline__ u64 pack2(float x) {
    u64 d;
    asm("mov.b64 %0, {%1, %1};" : "=l"(d) : "f"(x));
    return d;
}
__device__ __forceinline__ float2 unpack2(u64 v) {
    uint32_t lo, hi;
    asm("mov.b64 {%0, %1}, %2;" : "=r"(lo), "=r"(hi) : "l"(v));
    return make_float2(__uint_as_float(lo), __uint_as_float(hi));
}

// FMA-pipe exp2 (no MUFU). Valid for t <= ~127; clamped below at -126.
// Magic-number round-to-nearest; deg-6 poly on f in [-0.5,0.5], rel err ~1.2e-7.
// bits(fi)<<23 works because the magic's own contribution shifts out mod 2^32.
__device__ __forceinline__ float exp2_fast(float t) {
    t = fmaxf(t, -126.0f);
    float fi = t + 12582912.0f;              // 2^23 + 2^22
    float f  = t - (fi - 12582912.0f);       // f in [-0.5, 0.5]
    float p = 1.5403530393381606e-4f;
    p = fmaf(p, f, 1.3333558146428443e-3f);
    p = fmaf(p, f, 9.6181291076284770e-3f);
    p = fmaf(p, f, 5.5504108664821580e-2f);
    p = fmaf(p, f, 2.4022650695910070e-1f);
    p = fmaf(p, f, 6.9314718055994530e-1f);
    p = fmaf(p, f, 1.0f);
    return __uint_as_float(__float_as_int(p) + (__float_as_int(fi) << 23));
}

// ---------------------------------------------------------------------------
// Precision-split conversion: x -> hi(bf16) + lo(bf16)
// ---------------------------------------------------------------------------
__global__ void __launch_bounds__(256) conv_act(
    const float* __restrict__ x, __nv_bfloat16* __restrict__ hi,
    __nv_bfloat16* __restrict__ lo, int n4)
{
    int i = blockIdx.x * blockDim.x + threadIdx.x;
    if (i >= n4) return;
    float4 v = ((const float4*)x)[i];
    __nv_bfloat16 h0 = __float2bfloat16(v.x);
    __nv_bfloat16 h1 = __float2bfloat16(v.y);
    __nv_bfloat16 h2 = __float2bfloat16(v.z);
    __nv_bfloat16 h3 = __float2bfloat16(v.w);
    __nv_bfloat16 l0 = __float2bfloat16(v.x - __bfloat162float(h0));
    __nv_bfloat16 l1 = __float2bfloat16(v.y - __bfloat162float(h1));
    __nv_bfloat16 l2 = __float2bfloat16(v.z - __bfloat162float(h2));
    __nv_bfloat16 l3 = __float2bfloat16(v.w - __bfloat162float(h3));
    ((__nv_bfloat162*)hi)[2 * i]     = __halves2bfloat162(h0, h1);
    ((__nv_bfloat162*)hi)[2 * i + 1] = __halves2bfloat162(h2, h3);
    ((__nv_bfloat162*)lo)[2 * i]     = __halves2bfloat162(l0, l1);
    ((__nv_bfloat162*)lo)[2 * i + 1] = __halves2bfloat162(l2, l3);
}

// W[k][n] (fp32) -> Wt_hi[n][k], Wt_lo[n][k] (bf16), tiled transpose
__global__ void __launch_bounds__(256) conv_w(
    const float* __restrict__ W, __nv_bfloat16* __restrict__ th,
    __nv_bfloat16* __restrict__ tl)
{
    __shared__ float t[32][33];
    const int n0 = blockIdx.x * 32, k0 = blockIdx.y * 32;
#pragma unroll
    for (int j = 0; j < 4; j++)
        t[threadIdx.y + j * 8][threadIdx.x] =
            W[(size_t)(k0 + threadIdx.y + j * 8) * DIM + n0 + threadIdx.x];
    __syncthreads();
#pragma unroll
    for (int j = 0; j < 4; j++) {
        float v = t[threadIdx.x][threadIdx.y + j * 8];
        __nv_bfloat16 h = __float2bfloat16(v);
        __nv_bfloat16 l = __float2bfloat16(v - __bfloat162float(h));
        size_t o = (size_t)(n0 + threadIdx.y + j * 8) * DIM + k0 + threadIdx.x;
        th[o] = h;
        tl[o] = l;
    }
}

// ---------------------------------------------------------------------------
// mma.sync bf16x3 GEMM:  C[4096,1024] = (Ah+Al) @ (Wh+Wl)^T (+bias)*alpha
// CTA tile 128x128, 8 warps (2x4), warp tile 64x32, k-step 32.
// SMEM rows are 128B: [hi 64B | lo 64B], chunk-swizzled (c ^= r&7) for
// conflict-free ldmatrix. cp.async double buffer.
// ---------------------------------------------------------------------------
#define GEMM_SMEM 65536   // 2 stages * (A 16KB + W 16KB)
#define NKSTEP (DIM / 32) // 32

__device__ __forceinline__ void gemm_load_tile(
    uint32_t smb, const char* const* srcs, int kt, int s, int tid)
{
#pragma unroll
    for (int u = 0; u < 8; u++) {
        int idx  = u * 256 + tid;        // 0..2047
        int tile = idx >> 10;            // 0=A, 1=W
        int r    = (idx >> 3) & 127;
        int c    = idx & 7;              // chunk within 128B row
        const char* src = srcs[tile * 2 + (c >> 2)]
                        + (size_t)r * 2048 + kt * 64 + (c & 3) * 16;
        uint32_t dst = smb + s * 32768 + tile * 16384
                     + r * 128 + ((c ^ (r & 7)) << 4);
        cpasync16(dst, src);
    }
}

__device__ __forceinline__ void gemm_compute_stage(
    uint32_t smb, int s, int lane, int warp_m, int warp_n, float acc[4][4][4])
{
    const uint32_t abase = smb + s * 32768;
    const uint32_t wbase = abase + 16384;
    const int kh = lane >> 4;

#pragma unroll
    for (int kb = 0; kb < 2; kb++) {
        uint32_t a_h[4][4], a_l[4][4];
#pragma unroll
        for (int i = 0; i < 4; i++) {
            int rl = warp_m * 64 + i * 16 + (lane & 15);
            int ch0 = (kb * 2 + kh) ^ (rl & 7);
            int ch1 = (4 + kb * 2 + kh) ^ (rl & 7);
            ldsm4(a_h[i], abase + rl * 128 + (ch0 << 4));
            ldsm4(a_l[i], abase + rl * 128 + (ch1 << 4));
        }
        uint32_t b_h[4][2], b_l[4][2];
#pragma unroll
        for (int j2 = 0; j2 < 2; j2++) {
            int nl = warp_n * 32 + j2 * 16 + ((lane >> 3) & 1) * 8 + (lane & 7);
            int ch0 = (kb * 2 + kh) ^ (nl & 7);
            int ch1 = (4 + kb * 2 + kh) ^ (nl & 7);
            uint32_t t[4];
            ldsm4(t, wbase + nl * 128 + (ch0 << 4));
            b_h[j2 * 2][0]     = t[0]; b_h[j2 * 2][1]     = t[2];
            b_h[j2 * 2 + 1][0] = t[1]; b_h[j2 * 2 + 1][1] = t[3];
            ldsm4(t, wbase + nl * 128 + (ch1 << 4));
            b_l[j2 * 2][0]     = t[0]; b_l[j2 * 2][1]     = t[2];
            b_l[j2 * 2 + 1][0] = t[1]; b_l[j2 * 2 + 1][1] = t[3];
        }
#pragma unroll
        for (int i = 0; i < 4; i++)
#pragma unroll
            for (int jn = 0; jn < 4; jn++) {
                mma_bf16(acc[i][jn], a_h[i], b_h[jn]);
                mma_bf16(acc[i][jn], a_h[i], b_l[jn]);
                mma_bf16(acc[i][jn], a_l[i], b_h[jn]);
            }
    }
}

__global__ void __launch_bounds__(256) gemm_mma(
    const __nv_bfloat16* __restrict__ Ah, const __nv_bfloat16* __restrict__ Al,
    const __nv_bfloat16* __restrict__ Wh, const __nv_bfloat16* __restrict__ Wl,
    const float* __restrict__ bias, float* __restrict__ C, float alpha)
{
    extern __shared__ char sm[];
    const int tid = threadIdx.x;
    const int lane = tid & 31, wid = tid >> 5;
    const int bx = blockIdx.x, by = blockIdx.y;
    const int warp_m = wid & 1, warp_n = wid >> 1;
    const uint32_t smb = (uint32_t)__cvta_generic_to_shared(sm);

    const char* srcs[4] = {
        (const char*)Ah + (size_t)by * 128 * 2048,
        (const char*)Al + (size_t)by * 128 * 2048,
        (const char*)Wh + (size_t)bx * 128 * 2048,
        (const char*)Wl + (size_t)bx * 128 * 2048
    };

    float acc[4][4][4];
#pragma unroll
    for (int i = 0; i < 4; i++)
#pragma unroll
        for (int j = 0; j < 4; j++)
#pragma unroll
            for (int r = 0; r < 4; r++) acc[i][j][r] = 0.f;

    gemm_load_tile(smb, srcs, 0, 0, tid);
    asm volatile("cp.async.commit_group;" ::: "memory");
    gemm_load_tile(smb, srcs, 1, 1, tid);
    asm volatile("cp.async.commit_group;" ::: "memory");

#pragma unroll 1
    for (int kt = 0; kt < NKSTEP; kt++) {
        asm volatile("cp.async.wait_group 1;" ::: "memory");
        __syncthreads();
        gemm_compute_stage(smb, kt & 1, lane, warp_m, warp_n, acc);
        __syncthreads();
        if (kt + 2 < NKSTEP)
            gemm_load_tile(smb, srcs, kt + 2, kt & 1, tid);
        asm volatile("cp.async.commit_group;" ::: "memory");
    }

    // epilogue
    const int r0 = lane >> 2;
    const int c0 = (lane & 3) * 2;
#pragma unroll
    for (int jn = 0; jn < 4; jn++) {
        int col = bx * 128 + warp_n * 32 + jn * 8 + c0;
        float b0 = bias[col], b1 = bias[col + 1];
#pragma unroll
        for (int i = 0; i < 4; i++) {
            int row = by * 128 + warp_m * 64 + i * 16 + r0;
            float2 v0 = make_float2((acc[i][jn][0] + b0) * alpha,
                                    (acc[i][jn][1] + b1) * alpha);
            float2 v1 = make_float2((acc[i][jn][2] + b0) * alpha,
                                    (acc[i][jn][3] + b1) * alpha);
            *(float2*)(C + (size_t)row * DIM + col)       = v0;
            *(float2*)(C + (size_t)(row + 8) * DIM + col) = v1;
        }
    }
}

// ---------------------------------------------------------------------------
// Flash-style masked attention, fp32, FFMA2 + FMA-pipe exp2.
// Q is pre-scaled by 0.125*log2(e), so softmax runs in base-2 throughout.
// Grid: (H, SEQ/128, BATCH). Block: 128 threads; thread t owns one q-row.
// ---------------------------------------------------------------------------
__global__ void __launch_bounds__(128) attn_kernel(
    const float* __restrict__ Qp, const float* __restrict__ Kp,
    const float* __restrict__ Vp, const int* __restrict__ mask,
    float* __restrict__ ctx)
{
    __shared__ float Ks[64][68];
    __shared__ float Vs[64][68];

    const int tid = threadIdx.x;
    const int h  = blockIdx.x;
    const int qt = blockIdx.y;
    const int b  = blockIdx.z;
    const int qrow = qt * 128 + tid;

    u64 q2[32];
    const ulonglong2* qg =
        (const ulonglong2*)(Qp + ((size_t)(b * SEQ + qrow)) * DIM + h * DPH);
#pragma unroll
    for (int i = 0; i < 16; i++) {
        ulonglong2 v = qg[i];
        q2[2 * i] = v.x; q2[2 * i + 1] = v.y;
    }

    u64 o2[32];
#pragma unroll
    for (int i = 0; i < 32; i++) o2[i] = 0ull;   // (0.0f, 0.0f)

    float m = -1e30f, l = 0.f;
    const int* mrow = mask + ((size_t)(b * SEQ + qrow)) * SEQ;

    for (int k0 = 0; k0 < SEQ; k0 += 64) {
        __syncthreads();
#pragma unroll
        for (int it = 0; it < 8; it++) {
            int idx = it * 128 + tid;
            int row = idx >> 4;
            int c4  = idx & 15;
            size_t gofs = ((size_t)(b * SEQ + k0 + row)) * DIM + h * DPH + c4 * 4;
            *(float4*)&Ks[row][c4 * 4] = *(const float4*)(Kp + gofs);
            *(float4*)&Vs[row][c4 * 4] = *(const float4*)(Vp + gofs);
        }
        __syncthreads();

#pragma unroll 1
        for (int c = 0; c < 8; c++) {
            const int4 mk0 = *(const int4*)(mrow + k0 + c * 8);
            const int4 mk1 = *(const int4*)(mrow + k0 + c * 8 + 4);
            int mk[8] = { mk0.x, mk0.y, mk0.z, mk0.w, mk1.x, mk1.y, mk1.z, mk1.w };

            float s[8];
#pragma unroll
            for (int jj = 0; jj < 8; jj++) {
                const int j = c * 8 + jj;
                const ulonglong2* kr = (const ulonglong2*)&Ks[j][0];
                u64 a0 = 0ull, a1 = 0ull;
#pragma unroll
                for (int d8 = 0; d8 < 16; d8++) {
                    ulonglong2 kk = kr[d8];
                    a0 = ffma2(q2[2 * d8],     kk.x, a0);
                    a1 = ffma2(q2[2 * d8 + 1], kk.y, a1);
                }
                float2 f0 = unpack2(a0), f1 = unpack2(a1);
                float dot = (f0.x + f0.y) + (f1.x + f1.y);
                s[jj] = mk[jj] ? -1e30f : dot;
            }

            float cm = fmaxf(fmaxf(fmaxf(s[0], s[1]), fmaxf(s[2], s[3])),
                             fmaxf(fmaxf(s[4], s[5]), fmaxf(s[6], s[7])));
            float mnew = fmaxf(m, cm);
            if (mnew > m) {            // rare after warmup
                float corr = exp2_fast(m - mnew);
                u64 corr2 = pack2(corr);
                l *= corr;
#pragma unroll
                for (int i = 0; i < 32; i++) o2[i] = fmul2(corr2, o2[i]);
                m = mnew;
            }

            float p[8];
#pragma unroll
            for (int jj = 0; jj < 8; jj++) {
                p[jj] = mk[jj] ? 0.f : exp2_fast(s[jj] - m);
                l += p[jj];
            }

#pragma unroll
            for (int jj = 0; jj < 8; jj++) {
                const int j = c * 8 + jj;
                const u64 p2 = pack2(p[jj]);
                const ulonglong2* vr = (const ulonglong2*)&Vs[j][0];
#pragma unroll
                for (int d8 = 0; d8 < 16; d8++) {
                    ulonglong2 vv = vr[d8];
                    o2[2 * d8]     = ffma2(p2, vv.x, o2[2 * d8]);
                    o2[2 * d8 + 1] = ffma2(p2, vv.y, o2[2 * d8 + 1]);
                }
            }
        }
    }

    const float inv = 1.f / l;
    float* og = ctx + ((size_t)(b * SEQ + qrow)) * DIM + h * DPH;
#pragma unroll
    for (int i = 0; i < 32; i++) {
        float2 v = unpack2(o2[i]);
        float2 w = make_float2(v.x * inv, v.y * inv);
        *(float2*)(og + i * 2) = w;
    }
}

// ---------------------------------------------------------------------------
extern "C" void kernel_launch(void* const* d_in, const int* in_sizes, int n_in,
                              void* d_out, int out_size)
{
    (void)in_sizes; (void)n_in; (void)out_size;
    const float* key   = (const float*)d_in[0];
    const float* value = (const float*)d_in[1];
    const float* query = (const float*)d_in[2];
    const int*   mask  = (const int*)  d_in[3];
    const float* Wq = (const float*)d_in[4];
    const float* bq = (const float*)d_in[5];
    const float* Wk = (const float*)d_in[6];
    const float* bk = (const float*)d_in[7];
    const float* Wv = (const float*)d_in[8];
    const float* bv = (const float*)d_in[9];
    const float* Wo = (const float*)d_in[10];
    const float* bo = (const float*)d_in[11];
    float* out = (float*)d_out;

    float *gq, *gk, *gv, *gc;
    __nv_bfloat16 *gah, *gal, *gwh, *gwl;
    cudaGetSymbolAddress((void**)&gq, g_q);
    cudaGetSymbolAddress((void**)&gk, g_k);
    cudaGetSymbolAddress((void**)&gv, g_v);
    cudaGetSymbolAddress((void**)&gc, g_ctx);
    cudaGetSymbolAddress((void**)&gah, g_ah);
    cudaGetSymbolAddress((void**)&gal, g_al);
    cudaGetSymbolAddress((void**)&gwh, g_wh);
    cudaGetSymbolAddress((void**)&gwl, g_wl);

    cudaFuncSetAttribute(gemm_mma,
                         cudaFuncAttributeMaxDynamicSharedMemorySize, GEMM_SMEM);

    const dim3 ggrid(DIM / 128, MROWS / 128);       // (8, 32)
    const dim3 wgrid(32, 32);
    const dim3 wblk(32, 8);
    const int n4 = MROWS * DIM / 4;

    // Q projection: fold 1/sqrt(DPH) * log2(e) so softmax runs in base 2
    const float alpha_q = 0.125f * 1.4426950408889634f;
    conv_w<<<wgrid, wblk>>>(Wq, gwh, gwl);
    conv_act<<<n4 / 256, 256>>>(query, gah, gal, n4);
    gemm_mma<<<ggrid, 256, GEMM_SMEM>>>(gah, gal, gwh, gwl, bq, gq, alpha_q);

    // K projection
    conv_w<<<wgrid, wblk>>>(Wk, gwh, gwl);
    conv_act<<<n4 / 256, 256>>>(key, gah, gal, n4);
    gemm_mma<<<ggrid, 256, GEMM_SMEM>>>(gah, gal, gwh, gwl, bk, gk, 1.0f);

    // V projection
    conv_w<<<wgrid, wblk>>>(Wv, gwh, gwl);
    conv_act<<<n4 / 256, 256>>>(value, gah, gal, n4);
    gemm_mma<<<ggrid, 256, GEMM_SMEM>>>(gah, gal, gwh, gwl, bv, gv, 1.0f);

    // Attention
    attn_kernel<<<dim3(HEADS, SEQ / 128, BATCH), 128>>>(gq, gk, gv, mask, gc);

    // Output projection
    conv_w<<<wgrid, wblk>>>(Wo, gwh, gwl);
    conv_act<<<n4 / 256, 256>>>(gc, gah, gal, n4);
    gemm_mma<<<ggrid, 256, GEMM_SMEM>>>(gah, gal, gwh, gwl, bo, out, 1.0f);
}

// round 8
// speedup vs baseline: 2.4418x; 2.4418x over previous
#include <cuda_runtime.h>
#include <cuda_bf16.h>
#include <math.h>
#include <stdint.h>

// Problem constants (B=2, S=2048, D=1024, H=16, DPH=64)
#define BATCH 2
#define SEQ   2048
#define DIM   1024
#define HEADS 16
#define DPH   64
#define MROWS (BATCH * SEQ)   // 4096

typedef unsigned long long u64;

// ---------------------------------------------------------------------------
// Scratch (allocation-free rule: __device__ globals; 16B-aligned for cp.async)
// ---------------------------------------------------------------------------
__device__ __align__(16) __nv_bfloat16 g_ah[MROWS * DIM];    // activation hi / ctx hi
__device__ __align__(16) __nv_bfloat16 g_al[MROWS * DIM];    // activation lo / ctx lo
__device__ __align__(16) __nv_bfloat16 g_wh[DIM * DIM];      // W^T hi  [n][k]
__device__ __align__(16) __nv_bfloat16 g_wl[DIM * DIM];      // W^T lo  [n][k]
__device__ __align__(16) __nv_bfloat16 g_qh[MROWS * DIM], g_ql[MROWS * DIM];
__device__ __align__(16) __nv_bfloat16 g_kh[MROWS * DIM], g_kl[MROWS * DIM];
__device__ __align__(16) __nv_bfloat16 g_vh[MROWS * DIM], g_vl[MROWS * DIM];
__device__ __align__(16) __nv_bfloat16 g_mb[(size_t)BATCH * SEQ * SEQ];  // mask bias

// ---------------------------------------------------------------------------
// Baseline-ISA PTX helpers
// ---------------------------------------------------------------------------
__device__ __forceinline__ void cpasync16(uint32_t dst, const void* src) {
    asm volatile("cp.async.cg.shared.global [%0], [%1], 16;"
                 :: "r"(dst), "l"(src) : "memory");
}
__device__ __forceinline__ void ldsm4(uint32_t* r, uint32_t addr) {
    asm volatile("ldmatrix.sync.aligned.m8n8.x4.shared.b16 {%0,%1,%2,%3}, [%4];"
                 : "=r"(r[0]), "=r"(r[1]), "=r"(r[2]), "=r"(r[3]) : "r"(addr));
}
__device__ __forceinline__ void ldsm4t(uint32_t* r, uint32_t addr) {
    asm volatile("ldmatrix.sync.aligned.m8n8.x4.trans.shared.b16 {%0,%1,%2,%3}, [%4];"
                 : "=r"(r[0]), "=r"(r[1]), "=r"(r[2]), "=r"(r[3]) : "r"(addr));
}
__device__ __forceinline__ void mma_bf16(float* c, const uint32_t* a, const uint32_t* b) {
    asm volatile("mma.sync.aligned.m16n8k16.row.col.f32.bf16.bf16.f32 "
                 "{%0,%1,%2,%3}, {%4,%5,%6,%7}, {%8,%9}, {%0,%1,%2,%3};"
                 : "+f"(c[0]), "+f"(c[1]), "+f"(c[2]), "+f"(c[3])
                 : "r"(a[0]), "r"(a[1]), "r"(a[2]), "r"(a[3]),
                   "r"(b[0]), "r"(b[1]));
}
// MUFU exp2 (ex2.approx.f32)
__device__ __forceinline__ float exp2_mufu(float x) {
    float y;
    asm("ex2.approx.f32 %0, %1;" : "=f"(y) : "f"(x));
    return y;
}
// split (v0,v1) f32 pair -> bf16x2 hi word + bf16x2 residual word
__device__ __forceinline__ void splitpack(float v0, float v1, uint32_t& h, uint32_t& l) {
    asm("cvt.rn.bf16x2.f32 %0, %1, %2;" : "=r"(h) : "f"(v1), "f"(v0));
    float h0 = __uint_as_float(h << 16);
    float h1 = __uint_as_float(h & 0xFFFF0000u);
    asm("cvt.rn.bf16x2.f32 %0, %1, %2;" : "=r"(l) : "f"(v1 - h1), "f"(v0 - h0));
}

// ---------------------------------------------------------------------------
// conv_act: fp32 activations -> hi/lo bf16 (GEMM inputs)
// ---------------------------------------------------------------------------
__global__ void __launch_bounds__(256) conv_act(
    const float* __restrict__ x, __nv_bfloat16* __restrict__ hi,
    __nv_bfloat16* __restrict__ lo, int n4)
{
    int i = blockIdx.x * blockDim.x + threadIdx.x;
    if (i >= n4) return;
    float4 v = ((const float4*)x)[i];
    uint32_t h0, l0, h1, l1;
    splitpack(v.x, v.y, h0, l0);
    splitpack(v.z, v.w, h1, l1);
    ((uint2*)hi)[i] = make_uint2(h0, h1);
    ((uint2*)lo)[i] = make_uint2(l0, l1);
}

// W[k][n] fp32 -> W^T hi/lo bf16 [n][k]
__global__ void __launch_bounds__(256) conv_w(
    const float* __restrict__ W, __nv_bfloat16* __restrict__ th,
    __nv_bfloat16* __restrict__ tl)
{
    __shared__ float t[32][33];
    const int n0 = blockIdx.x * 32, k0 = blockIdx.y * 32;
#pragma unroll
    for (int j = 0; j < 4; j++)
        t[threadIdx.y + j * 8][threadIdx.x] =
            W[(size_t)(k0 + threadIdx.y + j * 8) * DIM + n0 + threadIdx.x];
    __syncthreads();
#pragma unroll
    for (int j = 0; j < 4; j++) {
        float v = t[threadIdx.x][threadIdx.y + j * 8];
        __nv_bfloat16 h = __float2bfloat16(v);
        __nv_bfloat16 l = __float2bfloat16(v - __bfloat162float(h));
        size_t o = (size_t)(n0 + threadIdx.y + j * 8) * DIM + k0 + threadIdx.x;
        th[o] = h;
        tl[o] = l;
    }
}

// bool/int mask -> additive bf16 bias (-16384 masked, 0 allowed)
__global__ void __launch_bounds__(256) conv_mask(
    const int* __restrict__ m, __nv_bfloat16* __restrict__ mb, int n4)
{
    int i = blockIdx.x * blockDim.x + threadIdx.x;
    if (i >= n4) return;
    int4 v = ((const int4*)m)[i];
    const __nv_bfloat16 NEG = __float2bfloat16(-16384.0f);
    const __nv_bfloat16 ZER = __float2bfloat16(0.0f);
    __nv_bfloat162 a = __halves2bfloat162(v.x ? NEG : ZER, v.y ? NEG : ZER);
    __nv_bfloat162 b = __halves2bfloat162(v.z ? NEG : ZER, v.w ? NEG : ZER);
    ((__nv_bfloat162*)mb)[2 * i]     = a;
    ((__nv_bfloat162*)mb)[2 * i + 1] = b;
}

// ---------------------------------------------------------------------------
// mma.sync bf16x3 GEMM:  C = (Ah+Al) @ (Wh+Wl)^T (+bias)*alpha
// Output: f32 (Cf) OR split bf16 hi/lo (Ch, Cl).
// ---------------------------------------------------------------------------
#define GEMM_SMEM 65536
#define NKSTEP (DIM / 32)

__device__ __forceinline__ void gemm_load_tile(
    uint32_t smb, const char* const* srcs, int kt, int s, int tid)
{
#pragma unroll
    for (int u = 0; u < 8; u++) {
        int idx  = u * 256 + tid;
        int tile = idx >> 10;
        int r    = (idx >> 3) & 127;
        int c    = idx & 7;
        const char* src = srcs[tile * 2 + (c >> 2)]
                        + (size_t)r * 2048 + kt * 64 + (c & 3) * 16;
        uint32_t dst = smb + s * 32768 + tile * 16384
                     + r * 128 + ((c ^ (r & 7)) << 4);
        cpasync16(dst, src);
    }
}

__device__ __forceinline__ void gemm_compute_stage(
    uint32_t smb, int s, int lane, int warp_m, int warp_n, float acc[4][4][4])
{
    const uint32_t abase = smb + s * 32768;
    const uint32_t wbase = abase + 16384;
    const int kh = lane >> 4;

#pragma unroll
    for (int kb = 0; kb < 2; kb++) {
        uint32_t a_h[4][4], a_l[4][4];
#pragma unroll
        for (int i = 0; i < 4; i++) {
            int rl = warp_m * 64 + i * 16 + (lane & 15);
            int ch0 = (kb * 2 + kh) ^ (rl & 7);
            int ch1 = (4 + kb * 2 + kh) ^ (rl & 7);
            ldsm4(a_h[i], abase + rl * 128 + (ch0 << 4));
            ldsm4(a_l[i], abase + rl * 128 + (ch1 << 4));
        }
        uint32_t b_h[4][2], b_l[4][2];
#pragma unroll
        for (int j2 = 0; j2 < 2; j2++) {
            int nl = warp_n * 32 + j2 * 16 + ((lane >> 3) & 1) * 8 + (lane & 7);
            int ch0 = (kb * 2 + kh) ^ (nl & 7);
            int ch1 = (4 + kb * 2 + kh) ^ (nl & 7);
            uint32_t t[4];
            ldsm4(t, wbase + nl * 128 + (ch0 << 4));
            b_h[j2 * 2][0]     = t[0]; b_h[j2 * 2][1]     = t[2];
            b_h[j2 * 2 + 1][0] = t[1]; b_h[j2 * 2 + 1][1] = t[3];
            ldsm4(t, wbase + nl * 128 + (ch1 << 4));
            b_l[j2 * 2][0]     = t[0]; b_l[j2 * 2][1]     = t[2];
            b_l[j2 * 2 + 1][0] = t[1]; b_l[j2 * 2 + 1][1] = t[3];
        }
#pragma unroll
        for (int i = 0; i < 4; i++)
#pragma unroll
            for (int jn = 0; jn < 4; jn++) {
                mma_bf16(acc[i][jn], a_h[i], b_h[jn]);
                mma_bf16(acc[i][jn], a_h[i], b_l[jn]);
                mma_bf16(acc[i][jn], a_l[i], b_h[jn]);
            }
    }
}

__global__ void __launch_bounds__(256) gemm_mma(
    const __nv_bfloat16* __restrict__ Ah, const __nv_bfloat16* __restrict__ Al,
    const __nv_bfloat16* __restrict__ Wh, const __nv_bfloat16* __restrict__ Wl,
    const float* __restrict__ bias, float* __restrict__ Cf,
    __nv_bfloat16* __restrict__ Ch, __nv_bfloat16* __restrict__ Cl, float alpha)
{
    extern __shared__ char sm[];
    const int tid = threadIdx.x;
    const int lane = tid & 31, wid = tid >> 5;
    const int bx = blockIdx.x, by = blockIdx.y;
    const int warp_m = wid & 1, warp_n = wid >> 1;
    const uint32_t smb = (uint32_t)__cvta_generic_to_shared(sm);

    const char* srcs[4] = {
        (const char*)Ah + (size_t)by * 128 * 2048,
        (const char*)Al + (size_t)by * 128 * 2048,
        (const char*)Wh + (size_t)bx * 128 * 2048,
        (const char*)Wl + (size_t)bx * 128 * 2048
    };

    float acc[4][4][4];
#pragma unroll
    for (int i = 0; i < 4; i++)
#pragma unroll
        for (int j = 0; j < 4; j++)
#pragma unroll
            for (int r = 0; r < 4; r++) acc[i][j][r] = 0.f;

    gemm_load_tile(smb, srcs, 0, 0, tid);
    asm volatile("cp.async.commit_group;" ::: "memory");
    gemm_load_tile(smb, srcs, 1, 1, tid);
    asm volatile("cp.async.commit_group;" ::: "memory");

#pragma unroll 1
    for (int kt = 0; kt < NKSTEP; kt++) {
        asm volatile("cp.async.wait_group 1;" ::: "memory");
        __syncthreads();
        gemm_compute_stage(smb, kt & 1, lane, warp_m, warp_n, acc);
        __syncthreads();
        if (kt + 2 < NKSTEP)
            gemm_load_tile(smb, srcs, kt + 2, kt & 1, tid);
        asm volatile("cp.async.commit_group;" ::: "memory");
    }

    const int r0 = lane >> 2;
    const int c0 = (lane & 3) * 2;
#pragma unroll
    for (int jn = 0; jn < 4; jn++) {
        int col = bx * 128 + warp_n * 32 + jn * 8 + c0;
        float b0 = bias[col], b1 = bias[col + 1];
#pragma unroll
        for (int i = 0; i < 4; i++) {
            int row = by * 128 + warp_m * 64 + i * 16 + r0;
            float v0 = (acc[i][jn][0] + b0) * alpha;
            float v1 = (acc[i][jn][1] + b1) * alpha;
            float v2 = (acc[i][jn][2] + b0) * alpha;
            float v3 = (acc[i][jn][3] + b1) * alpha;
            if (Cf) {
                *(float2*)(Cf + (size_t)row * DIM + col)       = make_float2(v0, v1);
                *(float2*)(Cf + (size_t)(row + 8) * DIM + col) = make_float2(v2, v3);
            } else {
                uint32_t h, l;
                splitpack(v0, v1, h, l);
                *(uint32_t*)(Ch + (size_t)row * DIM + col) = h;
                *(uint32_t*)(Cl + (size_t)row * DIM + col) = l;
                splitpack(v2, v3, h, l);
                *(uint32_t*)(Ch + (size_t)(row + 8) * DIM + col) = h;
                *(uint32_t*)(Cl + (size_t)(row + 8) * DIM + col) = l;
            }
        }
    }
}

// ---------------------------------------------------------------------------
// Tensor-core flash attention (bf16x3 HMMA, additive mask bias).
// CTA: 128 q-rows x 1 head. 8 warps x 16 q-rows. 64-key tiles, double buffer.
// smem: Q 32KB | KV stages 2x32KB (K hi|lo 16KB, V hi|lo 16KB). Total 96KB.
// ---------------------------------------------------------------------------
#define ATTN_SMEM 98304
#define NTILE (SEQ / 64)   // 32

__global__ void __launch_bounds__(256) attn_mma(
    const __nv_bfloat16* __restrict__ qh, const __nv_bfloat16* __restrict__ ql,
    const __nv_bfloat16* __restrict__ kh, const __nv_bfloat16* __restrict__ kl,
    const __nv_bfloat16* __restrict__ vh, const __nv_bfloat16* __restrict__ vl,
    const __nv_bfloat16* __restrict__ mb,
    __nv_bfloat16* __restrict__ oh, __nv_bfloat16* __restrict__ ol)
{
    extern __shared__ char sm[];
    const uint32_t smb = (uint32_t)__cvta_generic_to_shared(sm);
    const uint32_t QS = smb;
    const uint32_t KVS = smb + 32768;

    const int tid = threadIdx.x;
    const int lane = tid & 31, wid = tid >> 5;
    const int bx = blockIdx.x;        // q tile (of 128)
    const int hy = blockIdx.y;        // head
    const int bz = blockIdx.z;        // batch
    const int g = lane >> 2, t4 = lane & 3;

    const size_t qrow0 = (size_t)bz * SEQ + bx * 128;   // global row base
    const size_t colofs = (size_t)hy * DPH;

    // ---- stage Q (hi|lo), 8 cp.async per thread ----
#pragma unroll
    for (int u = 0; u < 8; u++) {
        int idx = u * 256 + tid;          // 0..2047
        int r  = idx & 127;
        int hl = (idx >> 7) & 1;
        int c  = idx >> 8;                // 0..7
        const __nv_bfloat16* src = (hl ? ql : qh) + (qrow0 + r) * DIM + colofs + c * 8;
        cpasync16(QS + r * 256 + hl * 128 + ((c ^ (r & 7)) << 4), src);
    }
    asm volatile("cp.async.commit_group;" ::: "memory");

    // ---- KV tile loader ----
#define LOAD_KV(tt, s) do {                                                    \
    int k0_ = (tt) * 64;                                                       \
    _Pragma("unroll")                                                          \
    for (int u = 0; u < 8; u++) {                                              \
        int idx = u * 256 + tid;                                               \
        int kv = idx >> 10;                                                    \
        int hl = (idx >> 9) & 1;                                               \
        int r  = (idx >> 3) & 63;                                              \
        int c  = idx & 7;                                                      \
        const __nv_bfloat16* src =                                             \
            (kv ? (hl ? vl : vh) : (hl ? kl : kh))                             \
            + ((size_t)bz * SEQ + k0_ + r) * DIM + colofs + c * 8;             \
        cpasync16(KVS + (s) * 32768 + kv * 16384 + r * 256 + hl * 128          \
                  + ((c ^ (r & 7)) << 4), src);                                \
    }                                                                          \
} while (0)

    LOAD_KV(0, 0);
    asm volatile("cp.async.commit_group;" ::: "memory");
    LOAD_KV(1, 1);
    asm volatile("cp.async.commit_group;" ::: "memory");

    asm volatile("cp.async.wait_group 1;" ::: "memory");  // Q + tile0 done
    __syncthreads();

    // ---- Q fragments (once) ----
    uint32_t Qh[4][4], Ql[4][4];
    {
        int rl = wid * 16 + (lane & 15);
#pragma unroll
        for (int k = 0; k < 4; k++) {
            int ch = (2 * k + (lane >> 4)) ^ (rl & 7);
            uint32_t a = QS + rl * 256 + (ch << 4);
            ldsm4(Qh[k], a);
            ldsm4(Ql[k], a + 128);
        }
    }

    float O[8][4];
#pragma unroll
    for (int j = 0; j < 8; j++)
#pragma unroll
        for (int r = 0; r < 4; r++) O[j][r] = 0.f;
    float m_g = -1e30f, m_g8 = -1e30f, l_g = 0.f, l_g8 = 0.f;

    const __nv_bfloat16* brow_g  = mb + ((size_t)bz * SEQ + bx * 128 + wid * 16 + g) * SEQ + 2 * t4;
    const __nv_bfloat16* brow_g8 = brow_g + 8 * SEQ;

#pragma unroll 1
    for (int t = 0; t < NTILE; t++) {
        if (t > 0) {
            asm volatile("cp.async.wait_group 1;" ::: "memory");
            __syncthreads();
        }
        const uint32_t stg = KVS + (t & 1) * 32768;

        // ---- C init from additive mask bias ----
        float C[8][4];
#pragma unroll
        for (int j = 0; j < 8; j++) {
            __nv_bfloat162 b0 = *(const __nv_bfloat162*)(brow_g  + t * 64 + j * 8);
            __nv_bfloat162 b1 = *(const __nv_bfloat162*)(brow_g8 + t * 64 + j * 8);
            float2 f0 = __bfloat1622float2(b0);
            float2 f1 = __bfloat1622float2(b1);
            C[j][0] = f0.x; C[j][1] = f0.y;
            C[j][2] = f1.x; C[j][3] = f1.y;
        }

        // ---- S = Q K^T (bf16x3) ----
        {
            int krl = ((lane >> 3) & 1) * 8 + (lane & 7);
#pragma unroll
            for (int j2 = 0; j2 < 4; j2++) {
                int rr = j2 * 16 + krl;
#pragma unroll
                for (int k = 0; k < 4; k++) {
                    int ch = (2 * k + (lane >> 4)) ^ (rr & 7);
                    uint32_t a = stg + rr * 256 + (ch << 4);
                    uint32_t th[4], tl[4];
                    ldsm4(th, a);
                    ldsm4(tl, a + 128);
                    uint32_t bh0[2] = { th[0], th[2] }, bh1[2] = { th[1], th[3] };
                    uint32_t bl0[2] = { tl[0], tl[2] }, bl1[2] = { tl[1], tl[3] };
                    mma_bf16(C[2 * j2],     Qh[k], bh0);
                    mma_bf16(C[2 * j2],     Ql[k], bh0);
                    mma_bf16(C[2 * j2],     Qh[k], bl0);
                    mma_bf16(C[2 * j2 + 1], Qh[k], bh1);
                    mma_bf16(C[2 * j2 + 1], Ql[k], bh1);
                    mma_bf16(C[2 * j2 + 1], Qh[k], bl1);
                }
            }
        }

        // ---- online softmax (base 2; Q pre-scaled by log2 e) ----
        float mx0 = -1e30f, mx1 = -1e30f;
#pragma unroll
        for (int j = 0; j < 8; j++) {
            mx0 = fmaxf(mx0, fmaxf(C[j][0], C[j][1]));
            mx1 = fmaxf(mx1, fmaxf(C[j][2], C[j][3]));
        }
        mx0 = fmaxf(mx0, __shfl_xor_sync(0xffffffffu, mx0, 1));
        mx0 = fmaxf(mx0, __shfl_xor_sync(0xffffffffu, mx0, 2));
        mx1 = fmaxf(mx1, __shfl_xor_sync(0xffffffffu, mx1, 1));
        mx1 = fmaxf(mx1, __shfl_xor_sync(0xffffffffu, mx1, 2));
        float mn0 = fmaxf(m_g, mx0), mn1 = fmaxf(m_g8, mx1);
        float cg = exp2_mufu(m_g - mn0), cg8 = exp2_mufu(m_g8 - mn1);
        m_g = mn0; m_g8 = mn1;

        float s0 = 0.f, s1 = 0.f;
#pragma unroll
        for (int j = 0; j < 8; j++) {
            C[j][0] = exp2_mufu(C[j][0] - mn0);
            C[j][1] = exp2_mufu(C[j][1] - mn0);
            C[j][2] = exp2_mufu(C[j][2] - mn1);
            C[j][3] = exp2_mufu(C[j][3] - mn1);
            s0 += C[j][0] + C[j][1];
            s1 += C[j][2] + C[j][3];
        }
        l_g  = l_g  * cg  + s0;
        l_g8 = l_g8 * cg8 + s1;
#pragma unroll
        for (int j = 0; j < 8; j++) {
            O[j][0] *= cg;  O[j][1] *= cg;
            O[j][2] *= cg8; O[j][3] *= cg8;
        }

        // ---- pack P -> bf16 hi/lo A-fragments ----
        uint32_t Ph[4][4], Pl[4][4];
#pragma unroll
        for (int k = 0; k < 4; k++)
#pragma unroll
            for (int rr = 0; rr < 4; rr++) {
                int j = 2 * k + (rr >> 1);
                int e = (rr & 1) * 2;
                splitpack(C[j][e], C[j][e + 1], Ph[k][rr], Pl[k][rr]);
            }

        // ---- O += P V (bf16x3), V via ldmatrix.trans ----
#pragma unroll
        for (int jd = 0; jd < 8; jd++) {
            uint32_t a0 = stg + 16384 + lane * 256 + (((jd) ^ (lane & 7)) << 4);
            uint32_t a1 = stg + 16384 + (lane + 32) * 256 + (((jd) ^ ((lane + 32) & 7)) << 4);
            uint32_t th0[4], th1[4], tl0[4], tl1[4];
            ldsm4t(th0, a0); ldsm4t(th1, a1);
            ldsm4t(tl0, a0 + 128); ldsm4t(tl1, a1 + 128);
            uint32_t Vh[4][2] = { {th0[0],th0[1]}, {th0[2],th0[3]},
                                  {th1[0],th1[1]}, {th1[2],th1[3]} };
            uint32_t Vl[4][2] = { {tl0[0],tl0[1]}, {tl0[2],tl0[3]},
                                  {tl1[0],tl1[1]}, {tl1[2],tl1[3]} };
#pragma unroll
            for (int k = 0; k < 4; k++) {
                mma_bf16(O[jd], Ph[k], Vh[k]);
                mma_bf16(O[jd], Pl[k], Vh[k]);
                mma_bf16(O[jd], Ph[k], Vl[k]);
            }
        }

        __syncthreads();
        if (t + 2 < NTILE) LOAD_KV(t + 2, t & 1);
        asm volatile("cp.async.commit_group;" ::: "memory");
    }

    // ---- epilogue: normalize, split to bf16 hi/lo, store ----
    l_g  += __shfl_xor_sync(0xffffffffu, l_g, 1);
    l_g  += __shfl_xor_sync(0xffffffffu, l_g, 2);
    l_g8 += __shfl_xor_sync(0xffffffffu, l_g8, 1);
    l_g8 += __shfl_xor_sync(0xffffffffu, l_g8, 2);
    float ig = 1.f / l_g, ig8 = 1.f / l_g8;

    size_t row_g  = qrow0 + wid * 16 + g;
    size_t off_g  = row_g * DIM + colofs + 2 * t4;
    size_t off_g8 = off_g + 8 * DIM;
#pragma unroll
    for (int jd = 0; jd < 8; jd++) {
        uint32_t h, l;
        splitpack(O[jd][0] * ig, O[jd][1] * ig, h, l);
        *(uint32_t*)(oh + off_g + jd * 8) = h;
        *(uint32_t*)(ol + off_g + jd * 8) = l;
        splitpack(O[jd][2] * ig8, O[jd][3] * ig8, h, l);
        *(uint32_t*)(oh + off_g8 + jd * 8) = h;
        *(uint32_t*)(ol + off_g8 + jd * 8) = l;
    }
#undef LOAD_KV
}

// ---------------------------------------------------------------------------
extern "C" void kernel_launch(void* const* d_in, const int* in_sizes, int n_in,
                              void* d_out, int out_size)
{
    (void)in_sizes; (void)n_in; (void)out_size;
    const float* key   = (const float*)d_in[0];
    const float* value = (const float*)d_in[1];
    const float* query = (const float*)d_in[2];
    const int*   mask  = (const int*)  d_in[3];
    const float* Wq = (const float*)d_in[4];
    const float* bq = (const float*)d_in[5];
    const float* Wk = (const float*)d_in[6];
    const float* bk = (const float*)d_in[7];
    const float* Wv = (const float*)d_in[8];
    const float* bv = (const float*)d_in[9];
    const float* Wo = (const float*)d_in[10];
    const float* bo = (const float*)d_in[11];
    float* out = (float*)d_out;

    __nv_bfloat16 *gah, *gal, *gwh, *gwl, *gqh, *gql, *gkh, *gkl, *gvh, *gvl, *gmb;
    cudaGetSymbolAddress((void**)&gah, g_ah);
    cudaGetSymbolAddress((void**)&gal, g_al);
    cudaGetSymbolAddress((void**)&gwh, g_wh);
    cudaGetSymbolAddress((void**)&gwl, g_wl);
    cudaGetSymbolAddress((void**)&gqh, g_qh);
    cudaGetSymbolAddress((void**)&gql, g_ql);
    cudaGetSymbolAddress((void**)&gkh, g_kh);
    cudaGetSymbolAddress((void**)&gkl, g_kl);
    cudaGetSymbolAddress((void**)&gvh, g_vh);
    cudaGetSymbolAddress((void**)&gvl, g_vl);
    cudaGetSymbolAddress((void**)&gmb, g_mb);

    cudaFuncSetAttribute(gemm_mma,
                         cudaFuncAttributeMaxDynamicSharedMemorySize, GEMM_SMEM);
    cudaFuncSetAttribute(attn_mma,
                         cudaFuncAttributeMaxDynamicSharedMemorySize, ATTN_SMEM);

    const dim3 ggrid(DIM / 128, MROWS / 128);       // (8, 32)
    const dim3 wgrid(32, 32);
    const dim3 wblk(32, 8);
    const int n4 = MROWS * DIM / 4;
    const int nm4 = BATCH * SEQ * SEQ / 4;

    // mask -> additive bias
    conv_mask<<<nm4 / 256, 256>>>(mask, gmb, nm4);

    // Q projection: fold 1/sqrt(DPH) * log2(e); split-bf16 output
    const float alpha_q = 0.125f * 1.4426950408889634f;
    conv_w<<<wgrid, wblk>>>(Wq, gwh, gwl);
    conv_act<<<n4 / 256, 256>>>(query, gah, gal, n4);
    gemm_mma<<<ggrid, 256, GEMM_SMEM>>>(gah, gal, gwh, gwl, bq, nullptr, gqh, gql, alpha_q);

    // K projection
    conv_w<<<wgrid, wblk>>>(Wk, gwh, gwl);
    conv_act<<<n4 / 256, 256>>>(key, gah, gal, n4);
    gemm_mma<<<ggrid, 256, GEMM_SMEM>>>(gah, gal, gwh, gwl, bk, nullptr, gkh, gkl, 1.0f);

    // V projection
    conv_w<<<wgrid, wblk>>>(Wv, gwh, gwl);
    conv_act<<<n4 / 256, 256>>>(value, gah, gal, n4);
    gemm_mma<<<ggrid, 256, GEMM_SMEM>>>(gah, gal, gwh, gwl, bv, nullptr, gvh, gvl, 1.0f);

    // Attention -> ctx split directly into out-projection inputs
    attn_mma<<<dim3(SEQ / 128, HEADS, BATCH), 256, ATTN_SMEM>>>(
        gqh, gql, gkh, gkl, gvh, gvl, gmb, gah, gal);

    // Output projection -> f32 out  (THE R7 BUG: this conv_w was missing)
    conv_w<<<wgrid, wblk>>>(Wo, gwh, gwl);
    gemm_mma<<<ggrid, 256, GEMM_SMEM>>>(gah, gal, gwh, gwl, bo, out, nullptr, nullptr, 1.0f);
}

// round 9
// speedup vs baseline: 3.1323x; 1.2828x over previous
#include <cuda_runtime.h>
#include <cuda_bf16.h>
#include <cuda_fp16.h>
#include <math.h>
#include <stdint.h>

// Problem constants (B=2, S=2048, D=1024, H=16, DPH=64)
#define BATCH 2
#define SEQ   2048
#define DIM   1024
#define HEADS 16
#define DPH   64
#define MROWS (BATCH * SEQ)   // 4096

// ---------------------------------------------------------------------------
// Scratch (allocation-free rule: __device__ globals; 16B-aligned for cp.async)
// ---------------------------------------------------------------------------
__device__ __align__(16) __nv_bfloat16 g_ah[MROWS * DIM];    // activation hi / ctx hi
__device__ __align__(16) __nv_bfloat16 g_al[MROWS * DIM];    // activation lo / ctx lo
__device__ __align__(16) __nv_bfloat16 g_wh[DIM * DIM];      // W^T hi  [n][k]
__device__ __align__(16) __nv_bfloat16 g_wl[DIM * DIM];      // W^T lo  [n][k]
__device__ __align__(16) __nv_bfloat16 g_qh[MROWS * DIM], g_ql[MROWS * DIM];
__device__ __align__(16) __nv_bfloat16 g_kh[MROWS * DIM], g_kl[MROWS * DIM];
__device__ __align__(16) __half       g_v16[MROWS * DIM];    // V projection, fp16
__device__ __align__(16) __nv_bfloat16 g_mb[(size_t)BATCH * SEQ * SEQ];  // mask bias

// ---------------------------------------------------------------------------
// Baseline-ISA PTX helpers
// ---------------------------------------------------------------------------
__device__ __forceinline__ void cpasync16(uint32_t dst, const void* src) {
    asm volatile("cp.async.cg.shared.global [%0], [%1], 16;"
                 :: "r"(dst), "l"(src) : "memory");
}
__device__ __forceinline__ void ldsm4(uint32_t* r, uint32_t addr) {
    asm volatile("ldmatrix.sync.aligned.m8n8.x4.shared.b16 {%0,%1,%2,%3}, [%4];"
                 : "=r"(r[0]), "=r"(r[1]), "=r"(r[2]), "=r"(r[3]) : "r"(addr));
}
__device__ __forceinline__ void ldsm4t(uint32_t* r, uint32_t addr) {
    asm volatile("ldmatrix.sync.aligned.m8n8.x4.trans.shared.b16 {%0,%1,%2,%3}, [%4];"
                 : "=r"(r[0]), "=r"(r[1]), "=r"(r[2]), "=r"(r[3]) : "r"(addr));
}
__device__ __forceinline__ void mma_bf16(float* c, const uint32_t* a, const uint32_t* b) {
    asm volatile("mma.sync.aligned.m16n8k16.row.col.f32.bf16.bf16.f32 "
                 "{%0,%1,%2,%3}, {%4,%5,%6,%7}, {%8,%9}, {%0,%1,%2,%3};"
                 : "+f"(c[0]), "+f"(c[1]), "+f"(c[2]), "+f"(c[3])
                 : "r"(a[0]), "r"(a[1]), "r"(a[2]), "r"(a[3]),
                   "r"(b[0]), "r"(b[1]));
}
__device__ __forceinline__ void mma_f16(float* c, const uint32_t* a, const uint32_t* b) {
    asm volatile("mma.sync.aligned.m16n8k16.row.col.f32.f16.f16.f32 "
                 "{%0,%1,%2,%3}, {%4,%5,%6,%7}, {%8,%9}, {%0,%1,%2,%3};"
                 : "+f"(c[0]), "+f"(c[1]), "+f"(c[2]), "+f"(c[3])
                 : "r"(a[0]), "r"(a[1]), "r"(a[2]), "r"(a[3]),
                   "r"(b[0]), "r"(b[1]));
}
// MUFU exp2 (ex2.approx.f32)
__device__ __forceinline__ float exp2_mufu(float x) {
    float y;
    asm("ex2.approx.f32 %0, %1;" : "=f"(y) : "f"(x));
    return y;
}
// pack (v0,v1) -> f16x2 word (v0 low half)
__device__ __forceinline__ uint32_t cvtf16x2(float v0, float v1) {
    uint32_t r;
    asm("cvt.rn.f16x2.f32 %0, %1, %2;" : "=r"(r) : "f"(v1), "f"(v0));
    return r;
}
// split (v0,v1) f32 pair -> bf16x2 hi word + bf16x2 residual word
__device__ __forceinline__ void splitpack(float v0, float v1, uint32_t& h, uint32_t& l) {
    asm("cvt.rn.bf16x2.f32 %0, %1, %2;" : "=r"(h) : "f"(v1), "f"(v0));
    float h0 = __uint_as_float(h << 16);
    float h1 = __uint_as_float(h & 0xFFFF0000u);
    asm("cvt.rn.bf16x2.f32 %0, %1, %2;" : "=r"(l) : "f"(v1 - h1), "f"(v0 - h0));
}

// ---------------------------------------------------------------------------
// conv_act: fp32 activations -> hi/lo bf16 (GEMM inputs)
// ---------------------------------------------------------------------------
__global__ void __launch_bounds__(256) conv_act(
    const float* __restrict__ x, __nv_bfloat16* __restrict__ hi,
    __nv_bfloat16* __restrict__ lo, int n4)
{
    int i = blockIdx.x * blockDim.x + threadIdx.x;
    if (i >= n4) return;
    float4 v = ((const float4*)x)[i];
    uint32_t h0, l0, h1, l1;
    splitpack(v.x, v.y, h0, l0);
    splitpack(v.z, v.w, h1, l1);
    ((uint2*)hi)[i] = make_uint2(h0, h1);
    ((uint2*)lo)[i] = make_uint2(l0, l1);
}

// W[k][n] fp32 -> W^T hi/lo bf16 [n][k]
__global__ void __launch_bounds__(256) conv_w(
    const float* __restrict__ W, __nv_bfloat16* __restrict__ th,
    __nv_bfloat16* __restrict__ tl)
{
    __shared__ float t[32][33];
    const int n0 = blockIdx.x * 32, k0 = blockIdx.y * 32;
#pragma unroll
    for (int j = 0; j < 4; j++)
        t[threadIdx.y + j * 8][threadIdx.x] =
            W[(size_t)(k0 + threadIdx.y + j * 8) * DIM + n0 + threadIdx.x];
    __syncthreads();
#pragma unroll
    for (int j = 0; j < 4; j++) {
        float v = t[threadIdx.x][threadIdx.y + j * 8];
        __nv_bfloat16 h = __float2bfloat16(v);
        __nv_bfloat16 l = __float2bfloat16(v - __bfloat162float(h));
        size_t o = (size_t)(n0 + threadIdx.y + j * 8) * DIM + k0 + threadIdx.x;
        th[o] = h;
        tl[o] = l;
    }
}

// bool/int mask -> additive bf16 bias (-16384 masked, 0 allowed)
__global__ void __launch_bounds__(256) conv_mask(
    const int* __restrict__ m, __nv_bfloat16* __restrict__ mb, int n4)
{
    int i = blockIdx.x * blockDim.x + threadIdx.x;
    if (i >= n4) return;
    int4 v = ((const int4*)m)[i];
    const __nv_bfloat16 NEG = __float2bfloat16(-16384.0f);
    const __nv_bfloat16 ZER = __float2bfloat16(0.0f);
    __nv_bfloat162 a = __halves2bfloat162(v.x ? NEG : ZER, v.y ? NEG : ZER);
    __nv_bfloat162 b = __halves2bfloat162(v.z ? NEG : ZER, v.w ? NEG : ZER);
    ((__nv_bfloat162*)mb)[2 * i]     = a;
    ((__nv_bfloat162*)mb)[2 * i + 1] = b;
}

// ---------------------------------------------------------------------------
// mma.sync bf16x3 GEMM:  C = (Ah+Al) @ (Wh+Wl)^T (+bias)*alpha
// CTA tile 128(M) x 256(N), 8 warps (2x4), warp tile 64x64, k-step 32.
// Output: f32 (Cf) OR split bf16 hi/lo (Ch,Cl) OR fp16 (Ch alone, Cl=null).
// ---------------------------------------------------------------------------
#define GSTAGE 49152              // A 16KB + W 32KB
#define GEMM_SMEM (2 * GSTAGE)    // 96KB
#define NKSTEP (DIM / 32)

__device__ __forceinline__ void gemm_load_tile(
    uint32_t smb, const char* const* srcs, int kt, int s, int tid)
{
#pragma unroll
    for (int u = 0; u < 12; u++) {
        int idx = u * 256 + tid;          // 0..3071
        if (u < 4) {                      // A tile: 128 rows x 128B
            int r = idx >> 3, c = idx & 7;
            const char* src = srcs[c >> 2]
                            + (size_t)r * 2048 + kt * 64 + (c & 3) * 16;
            cpasync16(smb + s * GSTAGE + r * 128 + ((c ^ (r & 7)) << 4), src);
        } else {                          // W tile: 256 rows x 128B
            int j = idx - 1024;
            int r = j >> 3, c = j & 7;
            const char* src = srcs[2 + (c >> 2)]
                            + (size_t)r * 2048 + kt * 64 + (c & 3) * 16;
            cpasync16(smb + s * GSTAGE + 16384 + r * 128 + ((c ^ (r & 7)) << 4), src);
        }
    }
}

__device__ __forceinline__ void gemm_compute_stage(
    uint32_t smb, int s, int lane, int warp_m, int warp_n, float acc[4][8][4])
{
    const uint32_t abase = smb + s * GSTAGE;
    const uint32_t wbase = abase + 16384;
    const int kh = lane >> 4;

#pragma unroll
    for (int kb = 0; kb < 2; kb++) {
        uint32_t a_h[4][4], a_l[4][4];
#pragma unroll
        for (int i = 0; i < 4; i++) {
            int rl = warp_m * 64 + i * 16 + (lane & 15);
            int ch0 = (kb * 2 + kh) ^ (rl & 7);
            int ch1 = (4 + kb * 2 + kh) ^ (rl & 7);
            ldsm4(a_h[i], abase + rl * 128 + (ch0 << 4));
            ldsm4(a_l[i], abase + rl * 128 + (ch1 << 4));
        }
        uint32_t b_h[8][2], b_l[8][2];
#pragma unroll
        for (int j2 = 0; j2 < 4; j2++) {
            int nl = warp_n * 64 + j2 * 16 + ((lane >> 3) & 1) * 8 + (lane & 7);
            int ch0 = (kb * 2 + kh) ^ (nl & 7);
            int ch1 = (4 + kb * 2 + kh) ^ (nl & 7);
            uint32_t t[4];
            ldsm4(t, wbase + nl * 128 + (ch0 << 4));
            b_h[j2 * 2][0]     = t[0]; b_h[j2 * 2][1]     = t[2];
            b_h[j2 * 2 + 1][0] = t[1]; b_h[j2 * 2 + 1][1] = t[3];
            ldsm4(t, wbase + nl * 128 + (ch1 << 4));
            b_l[j2 * 2][0]     = t[0]; b_l[j2 * 2][1]     = t[2];
            b_l[j2 * 2 + 1][0] = t[1]; b_l[j2 * 2 + 1][1] = t[3];
        }
#pragma unroll
        for (int i = 0; i < 4; i++)
#pragma unroll
            for (int jn = 0; jn < 8; jn++) {
                mma_bf16(acc[i][jn], a_h[i], b_h[jn]);
                mma_bf16(acc[i][jn], a_h[i], b_l[jn]);
                mma_bf16(acc[i][jn], a_l[i], b_h[jn]);
            }
    }
}

__global__ void __launch_bounds__(256) gemm_mma(
    const __nv_bfloat16* __restrict__ Ah, const __nv_bfloat16* __restrict__ Al,
    const __nv_bfloat16* __restrict__ Wh, const __nv_bfloat16* __restrict__ Wl,
    const float* __restrict__ bias, float* __restrict__ Cf,
    __nv_bfloat16* __restrict__ Ch, __nv_bfloat16* __restrict__ Cl, float alpha)
{
    extern __shared__ char sm[];
    const int tid = threadIdx.x;
    const int lane = tid & 31, wid = tid >> 5;
    const int bx = blockIdx.x, by = blockIdx.y;
    const int warp_m = wid & 1, warp_n = wid >> 1;
    const uint32_t smb = (uint32_t)__cvta_generic_to_shared(sm);

    const char* srcs[4] = {
        (const char*)Ah + (size_t)by * 128 * 2048,
        (const char*)Al + (size_t)by * 128 * 2048,
        (const char*)Wh + (size_t)bx * 256 * 2048,
        (const char*)Wl + (size_t)bx * 256 * 2048
    };

    float acc[4][8][4];
#pragma unroll
    for (int i = 0; i < 4; i++)
#pragma unroll
        for (int j = 0; j < 8; j++)
#pragma unroll
            for (int r = 0; r < 4; r++) acc[i][j][r] = 0.f;

    gemm_load_tile(smb, srcs, 0, 0, tid);
    asm volatile("cp.async.commit_group;" ::: "memory");
    gemm_load_tile(smb, srcs, 1, 1, tid);
    asm volatile("cp.async.commit_group;" ::: "memory");

#pragma unroll 1
    for (int kt = 0; kt < NKSTEP; kt++) {
        asm volatile("cp.async.wait_group 1;" ::: "memory");
        __syncthreads();
        gemm_compute_stage(smb, kt & 1, lane, warp_m, warp_n, acc);
        __syncthreads();
        if (kt + 2 < NKSTEP)
            gemm_load_tile(smb, srcs, kt + 2, kt & 1, tid);
        asm volatile("cp.async.commit_group;" ::: "memory");
    }

    const int r0 = lane >> 2;
    const int c0 = (lane & 3) * 2;
#pragma unroll
    for (int jn = 0; jn < 8; jn++) {
        int col = bx * 256 + warp_n * 64 + jn * 8 + c0;
        float b0 = bias[col], b1 = bias[col + 1];
#pragma unroll
        for (int i = 0; i < 4; i++) {
            int row = by * 128 + warp_m * 64 + i * 16 + r0;
            float v0 = (acc[i][jn][0] + b0) * alpha;
            float v1 = (acc[i][jn][1] + b1) * alpha;
            float v2 = (acc[i][jn][2] + b0) * alpha;
            float v3 = (acc[i][jn][3] + b1) * alpha;
            if (Cf) {
                *(float2*)(Cf + (size_t)row * DIM + col)       = make_float2(v0, v1);
                *(float2*)(Cf + (size_t)(row + 8) * DIM + col) = make_float2(v2, v3);
            } else if (Cl) {
                uint32_t h, l;
                splitpack(v0, v1, h, l);
                *(uint32_t*)(Ch + (size_t)row * DIM + col) = h;
                *(uint32_t*)(Cl + (size_t)row * DIM + col) = l;
                splitpack(v2, v3, h, l);
                *(uint32_t*)(Ch + (size_t)(row + 8) * DIM + col) = h;
                *(uint32_t*)(Cl + (size_t)(row + 8) * DIM + col) = l;
            } else {   // fp16 output (V projection)
                *(uint32_t*)(Ch + (size_t)row * DIM + col)       = cvtf16x2(v0, v1);
                *(uint32_t*)(Ch + (size_t)(row + 8) * DIM + col) = cvtf16x2(v2, v3);
            }
        }
    }
}

// ---------------------------------------------------------------------------
// Tensor-core flash attention. S = QK^T in bf16x3; P,V in fp16 (1 product).
// CTA: 128 q-rows x 1 head. 8 warps x 16 q-rows. 64-key tiles, double buffer.
// smem: Q 32KB | stages 2x(K 16KB + V 8KB) = 48KB. Total 80KB.
// ---------------------------------------------------------------------------
#define KVSTAGE 24576
#define ATTN_SMEM (32768 + 2 * KVSTAGE)   // 81920
#define NTILE (SEQ / 64)                  // 32

__global__ void __launch_bounds__(256) attn_mma(
    const __nv_bfloat16* __restrict__ qh, const __nv_bfloat16* __restrict__ ql,
    const __nv_bfloat16* __restrict__ kh, const __nv_bfloat16* __restrict__ kl,
    const __half* __restrict__ v16,
    const __nv_bfloat16* __restrict__ mb,
    __nv_bfloat16* __restrict__ oh, __nv_bfloat16* __restrict__ ol)
{
    extern __shared__ char sm[];
    const uint32_t smb = (uint32_t)__cvta_generic_to_shared(sm);
    const uint32_t QS = smb;
    const uint32_t KVS = smb + 32768;

    const int tid = threadIdx.x;
    const int lane = tid & 31, wid = tid >> 5;
    const int bx = blockIdx.x;        // q tile (of 128)
    const int hy = blockIdx.y;        // head
    const int bz = blockIdx.z;        // batch
    const int g = lane >> 2, t4 = lane & 3;

    const size_t qrow0 = (size_t)bz * SEQ + bx * 128;
    const size_t colofs = (size_t)hy * DPH;

    // ---- stage Q (hi|lo), 8 cp.async per thread ----
#pragma unroll
    for (int u = 0; u < 8; u++) {
        int idx = u * 256 + tid;          // 0..2047
        int r  = idx & 127;
        int hl = (idx >> 7) & 1;
        int c  = idx >> 8;                // 0..7
        const __nv_bfloat16* src = (hl ? ql : qh) + (qrow0 + r) * DIM + colofs + c * 8;
        cpasync16(QS + r * 256 + hl * 128 + ((c ^ (r & 7)) << 4), src);
    }
    asm volatile("cp.async.commit_group;" ::: "memory");

    // ---- KV tile loader: K hi/lo (1024 cp16) + V fp16 (512 cp16) ----
#define LOAD_KV(tt, s) do {                                                    \
    int k0_ = (tt) * 64;                                                       \
    _Pragma("unroll")                                                          \
    for (int u = 0; u < 6; u++) {                                              \
        int idx = u * 256 + tid;                                               \
        if (u < 4) {                                                           \
            int hl = (idx >> 9) & 1;                                           \
            int r  = (idx >> 3) & 63;                                          \
            int c  = idx & 7;                                                  \
            const __nv_bfloat16* src = (hl ? kl : kh)                          \
                + ((size_t)bz * SEQ + k0_ + r) * DIM + colofs + c * 8;         \
            cpasync16(KVS + (s) * KVSTAGE + r * 256 + hl * 128                 \
                      + ((c ^ (r & 7)) << 4), src);                            \
        } else {                                                               \
            int j = idx - 1024;                                                \
            int r = j >> 3, c = j & 7;                                         \
            const __half* src = v16                                            \
                + ((size_t)bz * SEQ + k0_ + r) * DIM + colofs + c * 8;         \
            cpasync16(KVS + (s) * KVSTAGE + 16384 + r * 128                    \
                      + ((c ^ (r & 7)) << 4), src);                            \
        }                                                                      \
    }                                                                          \
} while (0)

    LOAD_KV(0, 0);
    asm volatile("cp.async.commit_group;" ::: "memory");
    LOAD_KV(1, 1);
    asm volatile("cp.async.commit_group;" ::: "memory");

    asm volatile("cp.async.wait_group 1;" ::: "memory");  // Q + tile0 done
    __syncthreads();

    // ---- Q fragments (once) ----
    uint32_t Qh[4][4], Ql[4][4];
    {
        int rl = wid * 16 + (lane & 15);
#pragma unroll
        for (int k = 0; k < 4; k++) {
            int ch = (2 * k + (lane >> 4)) ^ (rl & 7);
            uint32_t a = QS + rl * 256 + (ch << 4);
            ldsm4(Qh[k], a);
            ldsm4(Ql[k], a + 128);
        }
    }

    float O[8][4];
#pragma unroll
    for (int j = 0; j < 8; j++)
#pragma unroll
        for (int r = 0; r < 4; r++) O[j][r] = 0.f;
    float m_g = -1e30f, m_g8 = -1e30f, l_g = 0.f, l_g8 = 0.f;

    const __nv_bfloat16* brow_g  = mb + ((size_t)bz * SEQ + bx * 128 + wid * 16 + g) * SEQ + 2 * t4;
    const __nv_bfloat16* brow_g8 = brow_g + 8 * SEQ;

#pragma unroll 1
    for (int t = 0; t < NTILE; t++) {
        if (t > 0) {
            asm volatile("cp.async.wait_group 1;" ::: "memory");
            __syncthreads();
        }
        const uint32_t stg = KVS + (t & 1) * KVSTAGE;

        // ---- C init from additive mask bias ----
        float C[8][4];
#pragma unroll
        for (int j = 0; j < 8; j++) {
            __nv_bfloat162 b0 = *(const __nv_bfloat162*)(brow_g  + t * 64 + j * 8);
            __nv_bfloat162 b1 = *(const __nv_bfloat162*)(brow_g8 + t * 64 + j * 8);
            float2 f0 = __bfloat1622float2(b0);
            float2 f1 = __bfloat1622float2(b1);
            C[j][0] = f0.x; C[j][1] = f0.y;
            C[j][2] = f1.x; C[j][3] = f1.y;
        }

        // ---- S = Q K^T (bf16x3) ----
        {
            int krl = ((lane >> 3) & 1) * 8 + (lane & 7);
#pragma unroll
            for (int j2 = 0; j2 < 4; j2++) {
                int rr = j2 * 16 + krl;
#pragma unroll
                for (int k = 0; k < 4; k++) {
                    int ch = (2 * k + (lane >> 4)) ^ (rr & 7);
                    uint32_t a = stg + rr * 256 + (ch << 4);
                    uint32_t th[4], tl[4];
                    ldsm4(th, a);
                    ldsm4(tl, a + 128);
                    uint32_t bh0[2] = { th[0], th[2] }, bh1[2] = { th[1], th[3] };
                    uint32_t bl0[2] = { tl[0], tl[2] }, bl1[2] = { tl[1], tl[3] };
                    mma_bf16(C[2 * j2],     Qh[k], bh0);
                    mma_bf16(C[2 * j2],     Ql[k], bh0);
                    mma_bf16(C[2 * j2],     Qh[k], bl0);
                    mma_bf16(C[2 * j2 + 1], Qh[k], bh1);
                    mma_bf16(C[2 * j2 + 1], Ql[k], bh1);
                    mma_bf16(C[2 * j2 + 1], Qh[k], bl1);
                }
            }
        }

        // ---- online softmax (base 2; Q pre-scaled by log2 e) ----
        float mx0 = -1e30f, mx1 = -1e30f;
#pragma unroll
        for (int j = 0; j < 8; j++) {
            mx0 = fmaxf(mx0, fmaxf(C[j][0], C[j][1]));
            mx1 = fmaxf(mx1, fmaxf(C[j][2], C[j][3]));
        }
        mx0 = fmaxf(mx0, __shfl_xor_sync(0xffffffffu, mx0, 1));
        mx0 = fmaxf(mx0, __shfl_xor_sync(0xffffffffu, mx0, 2));
        mx1 = fmaxf(mx1, __shfl_xor_sync(0xffffffffu, mx1, 1));
        mx1 = fmaxf(mx1, __shfl_xor_sync(0xffffffffu, mx1, 2));
        float mn0 = fmaxf(m_g, mx0), mn1 = fmaxf(m_g8, mx1);
        float cg = exp2_mufu(m_g - mn0), cg8 = exp2_mufu(m_g8 - mn1);
        m_g = mn0; m_g8 = mn1;

        float s0 = 0.f, s1 = 0.f;
#pragma unroll
        for (int j = 0; j < 8; j++) {
            C[j][0] = exp2_mufu(C[j][0] - mn0);
            C[j][1] = exp2_mufu(C[j][1] - mn0);
            C[j][2] = exp2_mufu(C[j][2] - mn1);
            C[j][3] = exp2_mufu(C[j][3] - mn1);
            s0 += C[j][0] + C[j][1];
            s1 += C[j][2] + C[j][3];
        }
        l_g  = l_g  * cg  + s0;
        l_g8 = l_g8 * cg8 + s1;
#pragma unroll
        for (int j = 0; j < 8; j++) {
            O[j][0] *= cg;  O[j][1] *= cg;
            O[j][2] *= cg8; O[j][3] *= cg8;
        }

        // ---- pack P -> fp16 A-fragments (single precision level) ----
        uint32_t Pf[4][4];
#pragma unroll
        for (int k = 0; k < 4; k++)
#pragma unroll
            for (int rr = 0; rr < 4; rr++) {
                int j = 2 * k + (rr >> 1);
                int e = (rr & 1) * 2;
                Pf[k][rr] = cvtf16x2(C[j][e], C[j][e + 1]);
            }

        // ---- O += P V (fp16 x fp16 -> f32), V via ldmatrix.trans ----
        const uint32_t vstg = stg + 16384;
#pragma unroll
        for (int jd = 0; jd < 8; jd++) {
            uint32_t a0 = vstg + lane * 128 + ((jd ^ (lane & 7)) << 4);
            uint32_t a1 = vstg + (lane + 32) * 128 + ((jd ^ (lane & 7)) << 4);
            uint32_t tv0[4], tv1[4];
            ldsm4t(tv0, a0);
            ldsm4t(tv1, a1);
            uint32_t Vf[4][2] = { {tv0[0],tv0[1]}, {tv0[2],tv0[3]},
                                  {tv1[0],tv1[1]}, {tv1[2],tv1[3]} };
#pragma unroll
            for (int k = 0; k < 4; k++)
                mma_f16(O[jd], Pf[k], Vf[k]);
        }

        __syncthreads();
        if (t + 2 < NTILE) LOAD_KV(t + 2, t & 1);
        asm volatile("cp.async.commit_group;" ::: "memory");
    }

    // ---- epilogue: normalize, split to bf16 hi/lo, store ----
    l_g  += __shfl_xor_sync(0xffffffffu, l_g, 1);
    l_g  += __shfl_xor_sync(0xffffffffu, l_g, 2);
    l_g8 += __shfl_xor_sync(0xffffffffu, l_g8, 1);
    l_g8 += __shfl_xor_sync(0xffffffffu, l_g8, 2);
    float ig = 1.f / l_g, ig8 = 1.f / l_g8;

    size_t row_g  = qrow0 + wid * 16 + g;
    size_t off_g  = row_g * DIM + colofs + 2 * t4;
    size_t off_g8 = off_g + 8 * DIM;
#pragma unroll
    for (int jd = 0; jd < 8; jd++) {
        uint32_t h, l;
        splitpack(O[jd][0] * ig, O[jd][1] * ig, h, l);
        *(uint32_t*)(oh + off_g + jd * 8) = h;
        *(uint32_t*)(ol + off_g + jd * 8) = l;
        splitpack(O[jd][2] * ig8, O[jd][3] * ig8, h, l);
        *(uint32_t*)(oh + off_g8 + jd * 8) = h;
        *(uint32_t*)(ol + off_g8 + jd * 8) = l;
    }
#undef LOAD_KV
}

// ---------------------------------------------------------------------------
extern "C" void kernel_launch(void* const* d_in, const int* in_sizes, int n_in,
                              void* d_out, int out_size)
{
    (void)in_sizes; (void)n_in; (void)out_size;
    const float* key   = (const float*)d_in[0];
    const float* value = (const float*)d_in[1];
    const float* query = (const float*)d_in[2];
    const int*   mask  = (const int*)  d_in[3];
    const float* Wq = (const float*)d_in[4];
    const float* bq = (const float*)d_in[5];
    const float* Wk = (const float*)d_in[6];
    const float* bk = (const float*)d_in[7];
    const float* Wv = (const float*)d_in[8];
    const float* bv = (const float*)d_in[9];
    const float* Wo = (const float*)d_in[10];
    const float* bo = (const float*)d_in[11];
    float* out = (float*)d_out;

    __nv_bfloat16 *gah, *gal, *gwh, *gwl, *gqh, *gql, *gkh, *gkl, *gmb;
    __half *gv16;
    cudaGetSymbolAddress((void**)&gah, g_ah);
    cudaGetSymbolAddress((void**)&gal, g_al);
    cudaGetSymbolAddress((void**)&gwh, g_wh);
    cudaGetSymbolAddress((void**)&gwl, g_wl);
    cudaGetSymbolAddress((void**)&gqh, g_qh);
    cudaGetSymbolAddress((void**)&gql, g_ql);
    cudaGetSymbolAddress((void**)&gkh, g_kh);
    cudaGetSymbolAddress((void**)&gkl, g_kl);
    cudaGetSymbolAddress((void**)&gv16, g_v16);
    cudaGetSymbolAddress((void**)&gmb, g_mb);

    cudaFuncSetAttribute(gemm_mma,
                         cudaFuncAttributeMaxDynamicSharedMemorySize, GEMM_SMEM);
    cudaFuncSetAttribute(attn_mma,
                         cudaFuncAttributeMaxDynamicSharedMemorySize, ATTN_SMEM);

    const dim3 ggrid(DIM / 256, MROWS / 128);       // (4, 32) = 128 CTAs
    const dim3 wgrid(32, 32);
    const dim3 wblk(32, 8);
    const int n4 = MROWS * DIM / 4;
    const int nm4 = BATCH * SEQ * SEQ / 4;

    // mask -> additive bias
    conv_mask<<<nm4 / 256, 256>>>(mask, gmb, nm4);

    // Q projection: fold 1/sqrt(DPH) * log2(e); split-bf16 output
    const float alpha_q = 0.125f * 1.4426950408889634f;
    conv_w<<<wgrid, wblk>>>(Wq, gwh, gwl);
    conv_act<<<n4 / 256, 256>>>(query, gah, gal, n4);
    gemm_mma<<<ggrid, 256, GEMM_SMEM>>>(gah, gal, gwh, gwl, bq, nullptr, gqh, gql, alpha_q);

    // K projection
    conv_w<<<wgrid, wblk>>>(Wk, gwh, gwl);
    conv_act<<<n4 / 256, 256>>>(key, gah, gal, n4);
    gemm_mma<<<ggrid, 256, GEMM_SMEM>>>(gah, gal, gwh, gwl, bk, nullptr, gkh, gkl, 1.0f);

    // V projection -> fp16 output
    conv_w<<<wgrid, wblk>>>(Wv, gwh, gwl);
    conv_act<<<n4 / 256, 256>>>(value, gah, gal, n4);
    gemm_mma<<<ggrid, 256, GEMM_SMEM>>>(gah, gal, gwh, gwl, bv, nullptr,
                                        (__nv_bfloat16*)gv16, nullptr, 1.0f);

    // Attention -> ctx split directly into out-projection inputs
    attn_mma<<<dim3(SEQ / 128, HEADS, BATCH), 256, ATTN_SMEM>>>(
        gqh, gql, gkh, gkl, gv16, gmb, gah, gal);

    // Output projection -> f32 out
    conv_w<<<wgrid, wblk>>>(Wo, gwh, gwl);
    gemm_mma<<<ggrid, 256, GEMM_SMEM>>>(gah, gal, gwh, gwl, bo, out, nullptr, nullptr, 1.0f);
}

// round 10
// speedup vs baseline: 3.3553x; 1.0712x over previous
#include <cuda_runtime.h>
#include <cuda_bf16.h>
#include <cuda_fp16.h>
#include <math.h>
#include <stdint.h>

// Problem constants (B=2, S=2048, D=1024, H=16, DPH=64)
#define BATCH 2
#define SEQ   2048
#define DIM   1024
#define HEADS 16
#define DPH   64
#define MROWS (BATCH * SEQ)   // 4096

// ---------------------------------------------------------------------------
// Scratch (allocation-free rule: __device__ globals; 16B-aligned for cp.async)
// ---------------------------------------------------------------------------
__device__ __align__(16) __nv_bfloat16 g_ah[MROWS * DIM];    // activation hi / ctx hi
__device__ __align__(16) __nv_bfloat16 g_al[MROWS * DIM];    // activation lo / ctx lo
__device__ __align__(16) __nv_bfloat16 g_wh[DIM * DIM];      // W^T hi  [n][k]
__device__ __align__(16) __nv_bfloat16 g_wl[DIM * DIM];      // W^T lo  [n][k]
__device__ __align__(16) __nv_bfloat16 g_qh[MROWS * DIM], g_ql[MROWS * DIM];
__device__ __align__(16) __nv_bfloat16 g_kh[MROWS * DIM], g_kl[MROWS * DIM];
__device__ __align__(16) __half       g_v16[MROWS * DIM];    // V projection, fp16
__device__ __align__(16) __nv_bfloat16 g_mb[(size_t)BATCH * SEQ * SEQ];  // mask bias

// ---------------------------------------------------------------------------
// Baseline-ISA PTX helpers
// ---------------------------------------------------------------------------
__device__ __forceinline__ void cpasync16(uint32_t dst, const void* src) {
    asm volatile("cp.async.cg.shared.global [%0], [%1], 16;"
                 :: "r"(dst), "l"(src) : "memory");
}
__device__ __forceinline__ void ldsm4(uint32_t* r, uint32_t addr) {
    asm volatile("ldmatrix.sync.aligned.m8n8.x4.shared.b16 {%0,%1,%2,%3}, [%4];"
                 : "=r"(r[0]), "=r"(r[1]), "=r"(r[2]), "=r"(r[3]) : "r"(addr));
}
__device__ __forceinline__ void ldsm4t(uint32_t* r, uint32_t addr) {
    asm volatile("ldmatrix.sync.aligned.m8n8.x4.trans.shared.b16 {%0,%1,%2,%3}, [%4];"
                 : "=r"(r[0]), "=r"(r[1]), "=r"(r[2]), "=r"(r[3]) : "r"(addr));
}
__device__ __forceinline__ void mma_bf16(float* c, const uint32_t* a, const uint32_t* b) {
    asm volatile("mma.sync.aligned.m16n8k16.row.col.f32.bf16.bf16.f32 "
                 "{%0,%1,%2,%3}, {%4,%5,%6,%7}, {%8,%9}, {%0,%1,%2,%3};"
                 : "+f"(c[0]), "+f"(c[1]), "+f"(c[2]), "+f"(c[3])
                 : "r"(a[0]), "r"(a[1]), "r"(a[2]), "r"(a[3]),
                   "r"(b[0]), "r"(b[1]));
}
__device__ __forceinline__ void mma_f16(float* c, const uint32_t* a, const uint32_t* b) {
    asm volatile("mma.sync.aligned.m16n8k16.row.col.f32.f16.f16.f32 "
                 "{%0,%1,%2,%3}, {%4,%5,%6,%7}, {%8,%9}, {%0,%1,%2,%3};"
                 : "+f"(c[0]), "+f"(c[1]), "+f"(c[2]), "+f"(c[3])
                 : "r"(a[0]), "r"(a[1]), "r"(a[2]), "r"(a[3]),
                   "r"(b[0]), "r"(b[1]));
}
// MUFU exp2 (ex2.approx.f32)
__device__ __forceinline__ float exp2_mufu(float x) {
    float y;
    asm("ex2.approx.f32 %0, %1;" : "=f"(y) : "f"(x));
    return y;
}
// pack (v0,v1) -> f16x2 word (v0 low half)
__device__ __forceinline__ uint32_t cvtf16x2(float v0, float v1) {
    uint32_t r;
    asm("cvt.rn.f16x2.f32 %0, %1, %2;" : "=r"(r) : "f"(v1), "f"(v0));
    return r;
}
// split (v0,v1) f32 pair -> bf16x2 hi word + bf16x2 residual word
__device__ __forceinline__ void splitpack(float v0, float v1, uint32_t& h, uint32_t& l) {
    asm("cvt.rn.bf16x2.f32 %0, %1, %2;" : "=r"(h) : "f"(v1), "f"(v0));
    float h0 = __uint_as_float(h << 16);
    float h1 = __uint_as_float(h & 0xFFFF0000u);
    asm("cvt.rn.bf16x2.f32 %0, %1, %2;" : "=r"(l) : "f"(v1 - h1), "f"(v0 - h0));
}

// ---------------------------------------------------------------------------
// conv_act: fp32 activations -> hi/lo bf16 (GEMM inputs)
// ---------------------------------------------------------------------------
__global__ void __launch_bounds__(256) conv_act(
    const float* __restrict__ x, __nv_bfloat16* __restrict__ hi,
    __nv_bfloat16* __restrict__ lo, int n4)
{
    int i = blockIdx.x * blockDim.x + threadIdx.x;
    if (i >= n4) return;
    float4 v = ((const float4*)x)[i];
    uint32_t h0, l0, h1, l1;
    splitpack(v.x, v.y, h0, l0);
    splitpack(v.z, v.w, h1, l1);
    ((uint2*)hi)[i] = make_uint2(h0, h1);
    ((uint2*)lo)[i] = make_uint2(l0, l1);
}

// W[k][n] fp32 -> W^T hi/lo bf16 [n][k]
__global__ void __launch_bounds__(256) conv_w(
    const float* __restrict__ W, __nv_bfloat16* __restrict__ th,
    __nv_bfloat16* __restrict__ tl)
{
    __shared__ float t[32][33];
    const int n0 = blockIdx.x * 32, k0 = blockIdx.y * 32;
#pragma unroll
    for (int j = 0; j < 4; j++)
        t[threadIdx.y + j * 8][threadIdx.x] =
            W[(size_t)(k0 + threadIdx.y + j * 8) * DIM + n0 + threadIdx.x];
    __syncthreads();
#pragma unroll
    for (int j = 0; j < 4; j++) {
        float v = t[threadIdx.x][threadIdx.y + j * 8];
        __nv_bfloat16 h = __float2bfloat16(v);
        __nv_bfloat16 l = __float2bfloat16(v - __bfloat162float(h));
        size_t o = (size_t)(n0 + threadIdx.y + j * 8) * DIM + k0 + threadIdx.x;
        th[o] = h;
        tl[o] = l;
    }
}

// bool/int mask -> additive bf16 bias (-16384 masked, 0 allowed)
__global__ void __launch_bounds__(256) conv_mask(
    const int* __restrict__ m, __nv_bfloat16* __restrict__ mb, int n4)
{
    int i = blockIdx.x * blockDim.x + threadIdx.x;
    if (i >= n4) return;
    int4 v = ((const int4*)m)[i];
    const __nv_bfloat16 NEG = __float2bfloat16(-16384.0f);
    const __nv_bfloat16 ZER = __float2bfloat16(0.0f);
    __nv_bfloat162 a = __halves2bfloat162(v.x ? NEG : ZER, v.y ? NEG : ZER);
    __nv_bfloat162 b = __halves2bfloat162(v.z ? NEG : ZER, v.w ? NEG : ZER);
    ((__nv_bfloat162*)mb)[2 * i]     = a;
    ((__nv_bfloat162*)mb)[2 * i + 1] = b;
}

// ---------------------------------------------------------------------------
// mma.sync bf16x3 GEMM:  C = (Ah+Al) @ (Wh+Wl)^T (+bias)*alpha
// CTA tile 128x128, 8 warps (2x4), warp tile 64x32, k-step 32.
// 3-stage cp.async pipeline, ONE __syncthreads per k-step.
// Output: f32 (Cf) OR split bf16 hi/lo (Ch,Cl) OR fp16 (Ch alone, Cl=null).
// ---------------------------------------------------------------------------
#define GSTAGE 32768               // A 16KB + W 16KB
#define GEMM_SMEM (3 * GSTAGE)     // 96KB, 2 CTAs/SM by smem
#define NKSTEP (DIM / 32)          // 32

__device__ __forceinline__ void gemm_load_tile(
    uint32_t smb, const char* const* srcs, int kt, int s, int tid)
{
#pragma unroll
    for (int u = 0; u < 8; u++) {
        int idx  = u * 256 + tid;
        int tile = idx >> 10;
        int r    = (idx >> 3) & 127;
        int c    = idx & 7;
        const char* src = srcs[tile * 2 + (c >> 2)]
                        + (size_t)r * 2048 + kt * 64 + (c & 3) * 16;
        uint32_t dst = smb + s * GSTAGE + tile * 16384
                     + r * 128 + ((c ^ (r & 7)) << 4);
        cpasync16(dst, src);
    }
}

__device__ __forceinline__ void gemm_compute_stage(
    uint32_t smb, int s, int lane, int warp_m, int warp_n, float acc[4][4][4])
{
    const uint32_t abase = smb + s * GSTAGE;
    const uint32_t wbase = abase + 16384;
    const int kh = lane >> 4;

#pragma unroll
    for (int kb = 0; kb < 2; kb++) {
        uint32_t a_h[4][4], a_l[4][4];
#pragma unroll
        for (int i = 0; i < 4; i++) {
            int rl = warp_m * 64 + i * 16 + (lane & 15);
            int ch0 = (kb * 2 + kh) ^ (rl & 7);
            int ch1 = (4 + kb * 2 + kh) ^ (rl & 7);
            ldsm4(a_h[i], abase + rl * 128 + (ch0 << 4));
            ldsm4(a_l[i], abase + rl * 128 + (ch1 << 4));
        }
        uint32_t b_h[4][2], b_l[4][2];
#pragma unroll
        for (int j2 = 0; j2 < 2; j2++) {
            int nl = warp_n * 32 + j2 * 16 + ((lane >> 3) & 1) * 8 + (lane & 7);
            int ch0 = (kb * 2 + kh) ^ (nl & 7);
            int ch1 = (4 + kb * 2 + kh) ^ (nl & 7);
            uint32_t t[4];
            ldsm4(t, wbase + nl * 128 + (ch0 << 4));
            b_h[j2 * 2][0]     = t[0]; b_h[j2 * 2][1]     = t[2];
            b_h[j2 * 2 + 1][0] = t[1]; b_h[j2 * 2 + 1][1] = t[3];
            ldsm4(t, wbase + nl * 128 + (ch1 << 4));
            b_l[j2 * 2][0]     = t[0]; b_l[j2 * 2][1]     = t[2];
            b_l[j2 * 2 + 1][0] = t[1]; b_l[j2 * 2 + 1][1] = t[3];
        }
#pragma unroll
        for (int i = 0; i < 4; i++)
#pragma unroll
            for (int jn = 0; jn < 4; jn++) {
                mma_bf16(acc[i][jn], a_h[i], b_h[jn]);
                mma_bf16(acc[i][jn], a_h[i], b_l[jn]);
                mma_bf16(acc[i][jn], a_l[i], b_h[jn]);
            }
    }
}

__global__ void __launch_bounds__(256) gemm_mma(
    const __nv_bfloat16* __restrict__ Ah, const __nv_bfloat16* __restrict__ Al,
    const __nv_bfloat16* __restrict__ Wh, const __nv_bfloat16* __restrict__ Wl,
    const float* __restrict__ bias, float* __restrict__ Cf,
    __nv_bfloat16* __restrict__ Ch, __nv_bfloat16* __restrict__ Cl, float alpha)
{
    extern __shared__ char sm[];
    const int tid = threadIdx.x;
    const int lane = tid & 31, wid = tid >> 5;
    const int bx = blockIdx.x, by = blockIdx.y;
    const int warp_m = wid & 1, warp_n = wid >> 1;
    const uint32_t smb = (uint32_t)__cvta_generic_to_shared(sm);

    const char* srcs[4] = {
        (const char*)Ah + (size_t)by * 128 * 2048,
        (const char*)Al + (size_t)by * 128 * 2048,
        (const char*)Wh + (size_t)bx * 128 * 2048,
        (const char*)Wl + (size_t)bx * 128 * 2048
    };

    float acc[4][4][4];
#pragma unroll
    for (int i = 0; i < 4; i++)
#pragma unroll
        for (int j = 0; j < 4; j++)
#pragma unroll
            for (int r = 0; r < 4; r++) acc[i][j][r] = 0.f;

    gemm_load_tile(smb, srcs, 0, 0, tid);
    asm volatile("cp.async.commit_group;" ::: "memory");
    gemm_load_tile(smb, srcs, 1, 1, tid);
    asm volatile("cp.async.commit_group;" ::: "memory");

    int sc = 0, sl = 2;    // compute stage, load stage (3-stage ring)
#pragma unroll 1
    for (int kt = 0; kt < NKSTEP; kt++) {
        asm volatile("cp.async.wait_group 1;" ::: "memory");
        __syncthreads();
        if (kt + 2 < NKSTEP)
            gemm_load_tile(smb, srcs, kt + 2, sl, tid);
        asm volatile("cp.async.commit_group;" ::: "memory");
        gemm_compute_stage(smb, sc, lane, warp_m, warp_n, acc);
        sc = (sc == 2) ? 0 : sc + 1;
        sl = (sl == 2) ? 0 : sl + 1;
    }

    const int r0 = lane >> 2;
    const int c0 = (lane & 3) * 2;
#pragma unroll
    for (int jn = 0; jn < 4; jn++) {
        int col = bx * 128 + warp_n * 32 + jn * 8 + c0;
        float b0 = bias[col], b1 = bias[col + 1];
#pragma unroll
        for (int i = 0; i < 4; i++) {
            int row = by * 128 + warp_m * 64 + i * 16 + r0;
            float v0 = (acc[i][jn][0] + b0) * alpha;
            float v1 = (acc[i][jn][1] + b1) * alpha;
            float v2 = (acc[i][jn][2] + b0) * alpha;
            float v3 = (acc[i][jn][3] + b1) * alpha;
            if (Cf) {
                *(float2*)(Cf + (size_t)row * DIM + col)       = make_float2(v0, v1);
                *(float2*)(Cf + (size_t)(row + 8) * DIM + col) = make_float2(v2, v3);
            } else if (Cl) {
                uint32_t h, l;
                splitpack(v0, v1, h, l);
                *(uint32_t*)(Ch + (size_t)row * DIM + col) = h;
                *(uint32_t*)(Cl + (size_t)row * DIM + col) = l;
                splitpack(v2, v3, h, l);
                *(uint32_t*)(Ch + (size_t)(row + 8) * DIM + col) = h;
                *(uint32_t*)(Cl + (size_t)(row + 8) * DIM + col) = l;
            } else {   // fp16 output (V projection)
                *(uint32_t*)(Ch + (size_t)row * DIM + col)       = cvtf16x2(v0, v1);
                *(uint32_t*)(Ch + (size_t)(row + 8) * DIM + col) = cvtf16x2(v2, v3);
            }
        }
    }
}

// ---------------------------------------------------------------------------
// Tensor-core flash attention. S = QK^T in bf16x3; P,V in fp16.
// CTA: 128 q-rows x 1 head. 8 warps x 16 q-rows. 64-key tiles.
// 3-stage KV pipeline, ONE __syncthreads per tile.
// smem: Q 32KB | 3 x (K 16KB + V 8KB) = 72KB. Total 104KB.
// ---------------------------------------------------------------------------
#define KVSTAGE 24576
#define ATTN_SMEM (32768 + 3 * KVSTAGE)   // 106496
#define NTILE (SEQ / 64)                  // 32

__global__ void __launch_bounds__(256) attn_mma(
    const __nv_bfloat16* __restrict__ qh, const __nv_bfloat16* __restrict__ ql,
    const __nv_bfloat16* __restrict__ kh, const __nv_bfloat16* __restrict__ kl,
    const __half* __restrict__ v16,
    const __nv_bfloat16* __restrict__ mb,
    __nv_bfloat16* __restrict__ oh, __nv_bfloat16* __restrict__ ol)
{
    extern __shared__ char sm[];
    const uint32_t smb = (uint32_t)__cvta_generic_to_shared(sm);
    const uint32_t QS = smb;
    const uint32_t KVS = smb + 32768;

    const int tid = threadIdx.x;
    const int lane = tid & 31, wid = tid >> 5;
    const int bx = blockIdx.x;        // q tile (of 128)
    const int hy = blockIdx.y;        // head
    const int bz = blockIdx.z;        // batch
    const int g = lane >> 2, t4 = lane & 3;

    const size_t qrow0 = (size_t)bz * SEQ + bx * 128;
    const size_t colofs = (size_t)hy * DPH;

    // ---- stage Q (hi|lo), 8 cp.async per thread ----
#pragma unroll
    for (int u = 0; u < 8; u++) {
        int idx = u * 256 + tid;          // 0..2047
        int r  = idx & 127;
        int hl = (idx >> 7) & 1;
        int c  = idx >> 8;                // 0..7
        const __nv_bfloat16* src = (hl ? ql : qh) + (qrow0 + r) * DIM + colofs + c * 8;
        cpasync16(QS + r * 256 + hl * 128 + ((c ^ (r & 7)) << 4), src);
    }
    asm volatile("cp.async.commit_group;" ::: "memory");

    // ---- KV tile loader: K hi/lo (1024 cp16) + V fp16 (512 cp16) ----
#define LOAD_KV(tt, s) do {                                                    \
    int k0_ = (tt) * 64;                                                       \
    _Pragma("unroll")                                                          \
    for (int u = 0; u < 6; u++) {                                              \
        int idx = u * 256 + tid;                                               \
        if (u < 4) {                                                           \
            int hl = (idx >> 9) & 1;                                           \
            int r  = (idx >> 3) & 63;                                          \
            int c  = idx & 7;                                                  \
            const __nv_bfloat16* src = (hl ? kl : kh)                          \
                + ((size_t)bz * SEQ + k0_ + r) * DIM + colofs + c * 8;         \
            cpasync16(KVS + (s) * KVSTAGE + r * 256 + hl * 128                 \
                      + ((c ^ (r & 7)) << 4), src);                            \
        } else {                                                               \
            int j = idx - 1024;                                                \
            int r = j >> 3, c = j & 7;                                         \
            const __half* src = v16                                            \
                + ((size_t)bz * SEQ + k0_ + r) * DIM + colofs + c * 8;         \
            cpasync16(KVS + (s) * KVSTAGE + 16384 + r * 128                    \
                      + ((c ^ (r & 7)) << 4), src);                            \
        }                                                                      \
    }                                                                          \
} while (0)

    LOAD_KV(0, 0);
    asm volatile("cp.async.commit_group;" ::: "memory");
    LOAD_KV(1, 1);
    asm volatile("cp.async.commit_group;" ::: "memory");

    // Q done (2 most recent groups may pend), then pull Q fragments once.
    asm volatile("cp.async.wait_group 2;" ::: "memory");
    __syncthreads();

    uint32_t Qh[4][4], Ql[4][4];
    {
        int rl = wid * 16 + (lane & 15);
#pragma unroll
        for (int k = 0; k < 4; k++) {
            int ch = (2 * k + (lane >> 4)) ^ (rl & 7);
            uint32_t a = QS + rl * 256 + (ch << 4);
            ldsm4(Qh[k], a);
            ldsm4(Ql[k], a + 128);
        }
    }

    float O[8][4];
#pragma unroll
    for (int j = 0; j < 8; j++)
#pragma unroll
        for (int r = 0; r < 4; r++) O[j][r] = 0.f;
    float m_g = -1e30f, m_g8 = -1e30f, l_g = 0.f, l_g8 = 0.f;

    const __nv_bfloat16* brow_g  = mb + ((size_t)bz * SEQ + bx * 128 + wid * 16 + g) * SEQ + 2 * t4;
    const __nv_bfloat16* brow_g8 = brow_g + 8 * SEQ;

    int sc = 0, sl = 2;    // compute stage, load stage (3-stage ring)
#pragma unroll 1
    for (int t = 0; t < NTILE; t++) {
        asm volatile("cp.async.wait_group 1;" ::: "memory");
        __syncthreads();
        if (t + 2 < NTILE) LOAD_KV(t + 2, sl);
        asm volatile("cp.async.commit_group;" ::: "memory");
        const uint32_t stg = KVS + sc * KVSTAGE;

        // ---- C init from additive mask bias ----
        float C[8][4];
#pragma unroll
        for (int j = 0; j < 8; j++) {
            __nv_bfloat162 b0 = *(const __nv_bfloat162*)(brow_g  + t * 64 + j * 8);
            __nv_bfloat162 b1 = *(const __nv_bfloat162*)(brow_g8 + t * 64 + j * 8);
            float2 f0 = __bfloat1622float2(b0);
            float2 f1 = __bfloat1622float2(b1);
            C[j][0] = f0.x; C[j][1] = f0.y;
            C[j][2] = f1.x; C[j][3] = f1.y;
        }

        // ---- S = Q K^T (bf16x3) ----
        {
            int krl = ((lane >> 3) & 1) * 8 + (lane & 7);
#pragma unroll
            for (int j2 = 0; j2 < 4; j2++) {
                int rr = j2 * 16 + krl;
#pragma unroll
                for (int k = 0; k < 4; k++) {
                    int ch = (2 * k + (lane >> 4)) ^ (rr & 7);
                    uint32_t a = stg + rr * 256 + (ch << 4);
                    uint32_t th[4], tl[4];
                    ldsm4(th, a);
                    ldsm4(tl, a + 128);
                    uint32_t bh0[2] = { th[0], th[2] }, bh1[2] = { th[1], th[3] };
                    uint32_t bl0[2] = { tl[0], tl[2] }, bl1[2] = { tl[1], tl[3] };
                    mma_bf16(C[2 * j2],     Qh[k], bh0);
                    mma_bf16(C[2 * j2],     Ql[k], bh0);
                    mma_bf16(C[2 * j2],     Qh[k], bl0);
                    mma_bf16(C[2 * j2 + 1], Qh[k], bh1);
                    mma_bf16(C[2 * j2 + 1], Ql[k], bh1);
                    mma_bf16(C[2 * j2 + 1], Qh[k], bl1);
                }
            }
        }

        // ---- online softmax (base 2; Q pre-scaled by log2 e) ----
        float mx0 = -1e30f, mx1 = -1e30f;
#pragma unroll
        for (int j = 0; j < 8; j++) {
            mx0 = fmaxf(mx0, fmaxf(C[j][0], C[j][1]));
            mx1 = fmaxf(mx1, fmaxf(C[j][2], C[j][3]));
        }
        mx0 = fmaxf(mx0, __shfl_xor_sync(0xffffffffu, mx0, 1));
        mx0 = fmaxf(mx0, __shfl_xor_sync(0xffffffffu, mx0, 2));
        mx1 = fmaxf(mx1, __shfl_xor_sync(0xffffffffu, mx1, 1));
        mx1 = fmaxf(mx1, __shfl_xor_sync(0xffffffffu, mx1, 2));
        float mn0 = fmaxf(m_g, mx0), mn1 = fmaxf(m_g8, mx1);
        float cg = exp2_mufu(m_g - mn0), cg8 = exp2_mufu(m_g8 - mn1);
        m_g = mn0; m_g8 = mn1;

        float s0 = 0.f, s1 = 0.f;
#pragma unroll
        for (int j = 0; j < 8; j++) {
            C[j][0] = exp2_mufu(C[j][0] - mn0);
            C[j][1] = exp2_mufu(C[j][1] - mn0);
            C[j][2] = exp2_mufu(C[j][2] - mn1);
            C[j][3] = exp2_mufu(C[j][3] - mn1);
            s0 += C[j][0] + C[j][1];
            s1 += C[j][2] + C[j][3];
        }
        l_g  = l_g  * cg  + s0;
        l_g8 = l_g8 * cg8 + s1;
#pragma unroll
        for (int j = 0; j < 8; j++) {
            O[j][0] *= cg;  O[j][1] *= cg;
            O[j][2] *= cg8; O[j][3] *= cg8;
        }

        // ---- pack P -> fp16 A-fragments ----
        uint32_t Pf[4][4];
#pragma unroll
        for (int k = 0; k < 4; k++)
#pragma unroll
            for (int rr = 0; rr < 4; rr++) {
                int j = 2 * k + (rr >> 1);
                int e = (rr & 1) * 2;
                Pf[k][rr] = cvtf16x2(C[j][e], C[j][e + 1]);
            }

        // ---- O += P V (fp16), V via ldmatrix.trans ----
        const uint32_t vstg = stg + 16384;
#pragma unroll
        for (int jd = 0; jd < 8; jd++) {
            uint32_t a0 = vstg + lane * 128 + ((jd ^ (lane & 7)) << 4);
            uint32_t a1 = vstg + (lane + 32) * 128 + ((jd ^ (lane & 7)) << 4);
            uint32_t tv0[4], tv1[4];
            ldsm4t(tv0, a0);
            ldsm4t(tv1, a1);
            uint32_t Vf[4][2] = { {tv0[0],tv0[1]}, {tv0[2],tv0[3]},
                                  {tv1[0],tv1[1]}, {tv1[2],tv1[3]} };
#pragma unroll
            for (int k = 0; k < 4; k++)
                mma_f16(O[jd], Pf[k], Vf[k]);
        }

        sc = (sc == 2) ? 0 : sc + 1;
        sl = (sl == 2) ? 0 : sl + 1;
    }

    // ---- epilogue: normalize, split to bf16 hi/lo, store ----
    l_g  += __shfl_xor_sync(0xffffffffu, l_g, 1);
    l_g  += __shfl_xor_sync(0xffffffffu, l_g, 2);
    l_g8 += __shfl_xor_sync(0xffffffffu, l_g8, 1);
    l_g8 += __shfl_xor_sync(0xffffffffu, l_g8, 2);
    float ig = 1.f / l_g, ig8 = 1.f / l_g8;

    size_t row_g  = qrow0 + wid * 16 + g;
    size_t off_g  = row_g * DIM + colofs + 2 * t4;
    size_t off_g8 = off_g + 8 * DIM;
#pragma unroll
    for (int jd = 0; jd < 8; jd++) {
        uint32_t h, l;
        splitpack(O[jd][0] * ig, O[jd][1] * ig, h, l);
        *(uint32_t*)(oh + off_g + jd * 8) = h;
        *(uint32_t*)(ol + off_g + jd * 8) = l;
        splitpack(O[jd][2] * ig8, O[jd][3] * ig8, h, l);
        *(uint32_t*)(oh + off_g8 + jd * 8) = h;
        *(uint32_t*)(ol + off_g8 + jd * 8) = l;
    }
#undef LOAD_KV
}

// ---------------------------------------------------------------------------
extern "C" void kernel_launch(void* const* d_in, const int* in_sizes, int n_in,
                              void* d_out, int out_size)
{
    (void)in_sizes; (void)n_in; (void)out_size;
    const float* key   = (const float*)d_in[0];
    const float* value = (const float*)d_in[1];
    const float* query = (const float*)d_in[2];
    const int*   mask  = (const int*)  d_in[3];
    const float* Wq = (const float*)d_in[4];
    const float* bq = (const float*)d_in[5];
    const float* Wk = (const float*)d_in[6];
    const float* bk = (const float*)d_in[7];
    const float* Wv = (const float*)d_in[8];
    const float* bv = (const float*)d_in[9];
    const float* Wo = (const float*)d_in[10];
    const float* bo = (const float*)d_in[11];
    float* out = (float*)d_out;

    __nv_bfloat16 *gah, *gal, *gwh, *gwl, *gqh, *gql, *gkh, *gkl, *gmb;
    __half *gv16;
    cudaGetSymbolAddress((void**)&gah, g_ah);
    cudaGetSymbolAddress((void**)&gal, g_al);
    cudaGetSymbolAddress((void**)&gwh, g_wh);
    cudaGetSymbolAddress((void**)&gwl, g_wl);
    cudaGetSymbolAddress((void**)&gqh, g_qh);
    cudaGetSymbolAddress((void**)&gql, g_ql);
    cudaGetSymbolAddress((void**)&gkh, g_kh);
    cudaGetSymbolAddress((void**)&gkl, g_kl);
    cudaGetSymbolAddress((void**)&gv16, g_v16);
    cudaGetSymbolAddress((void**)&gmb, g_mb);

    cudaFuncSetAttribute(gemm_mma,
                         cudaFuncAttributeMaxDynamicSharedMemorySize, GEMM_SMEM);
    cudaFuncSetAttribute(attn_mma,
                         cudaFuncAttributeMaxDynamicSharedMemorySize, ATTN_SMEM);

    const dim3 ggrid(DIM / 128, MROWS / 128);       // (8, 32) = 256 CTAs
    const dim3 wgrid(32, 32);
    const dim3 wblk(32, 8);
    const int n4 = MROWS * DIM / 4;
    const int nm4 = BATCH * SEQ * SEQ / 4;

    // mask -> additive bias
    conv_mask<<<nm4 / 256, 256>>>(mask, gmb, nm4);

    // Q projection: fold 1/sqrt(DPH) * log2(e); split-bf16 output
    const float alpha_q = 0.125f * 1.4426950408889634f;
    conv_w<<<wgrid, wblk>>>(Wq, gwh, gwl);
    conv_act<<<n4 / 256, 256>>>(query, gah, gal, n4);
    gemm_mma<<<ggrid, 256, GEMM_SMEM>>>(gah, gal, gwh, gwl, bq, nullptr, gqh, gql, alpha_q);

    // K projection
    conv_w<<<wgrid, wblk>>>(Wk, gwh, gwl);
    conv_act<<<n4 / 256, 256>>>(key, gah, gal, n4);
    gemm_mma<<<ggrid, 256, GEMM_SMEM>>>(gah, gal, gwh, gwl, bk, nullptr, gkh, gkl, 1.0f);

    // V projection -> fp16 output
    conv_w<<<wgrid, wblk>>>(Wv, gwh, gwl);
    conv_act<<<n4 / 256, 256>>>(value, gah, gal, n4);
    gemm_mma<<<ggrid, 256, GEMM_SMEM>>>(gah, gal, gwh, gwl, bv, nullptr,
                                        (__nv_bfloat16*)gv16, nullptr, 1.0f);

    // Attention -> ctx split directly into out-projection inputs
    attn_mma<<<dim3(SEQ / 128, HEADS, BATCH), 256, ATTN_SMEM>>>(
        gqh, gql, gkh, gkl, gv16, gmb, gah, gal);

    // Output projection -> f32 out
    conv_w<<<wgrid, wblk>>>(Wo, gwh, gwl);
    gemm_mma<<<ggrid, 256, GEMM_SMEM>>>(gah, gal, gwh, gwl, bo, out, nullptr, nullptr, 1.0f);
}

// round 11
// speedup vs baseline: 4.0855x; 1.2176x over previous
#include <cuda_runtime.h>
#include <cuda_bf16.h>
#include <cuda_fp16.h>
#include <math.h>
#include <stdint.h>

// Problem constants (B=2, S=2048, D=1024, H=16, DPH=64)
#define BATCH 2
#define SEQ   2048
#define DIM   1024
#define HEADS 16
#define DPH   64
#define MROWS (BATCH * SEQ)   // 4096

// ---------------------------------------------------------------------------
// Scratch (allocation-free rule: __device__ globals; 16B-aligned for cp.async)
// ---------------------------------------------------------------------------
__device__ __align__(16) __half g_ah[MROWS * DIM];   // activation hi / ctx hi
__device__ __align__(16) __half g_al[MROWS * DIM];   // activation lo / ctx lo
__device__ __align__(16) __half g_w16[DIM * DIM];    // W^T fp16 single [n][k]
__device__ __align__(16) __half g_qh[MROWS * DIM], g_ql[MROWS * DIM];
__device__ __align__(16) __half g_k16[MROWS * DIM];  // K fp16 single
__device__ __align__(16) __half g_v16[MROWS * DIM];  // V fp16 single
__device__ __align__(16) __nv_bfloat16 g_mb[(size_t)BATCH * SEQ * SEQ];  // mask bias

// ---------------------------------------------------------------------------
// Baseline-ISA PTX helpers
// ---------------------------------------------------------------------------
__device__ __forceinline__ void cpasync16(uint32_t dst, const void* src) {
    asm volatile("cp.async.cg.shared.global [%0], [%1], 16;"
                 :: "r"(dst), "l"(src) : "memory");
}
__device__ __forceinline__ void ldsm4(uint32_t* r, uint32_t addr) {
    asm volatile("ldmatrix.sync.aligned.m8n8.x4.shared.b16 {%0,%1,%2,%3}, [%4];"
                 : "=r"(r[0]), "=r"(r[1]), "=r"(r[2]), "=r"(r[3]) : "r"(addr));
}
__device__ __forceinline__ void ldsm4t(uint32_t* r, uint32_t addr) {
    asm volatile("ldmatrix.sync.aligned.m8n8.x4.trans.shared.b16 {%0,%1,%2,%3}, [%4];"
                 : "=r"(r[0]), "=r"(r[1]), "=r"(r[2]), "=r"(r[3]) : "r"(addr));
}
__device__ __forceinline__ void mma_f16(float* c, const uint32_t* a, const uint32_t* b) {
    asm volatile("mma.sync.aligned.m16n8k16.row.col.f32.f16.f16.f32 "
                 "{%0,%1,%2,%3}, {%4,%5,%6,%7}, {%8,%9}, {%0,%1,%2,%3};"
                 : "+f"(c[0]), "+f"(c[1]), "+f"(c[2]), "+f"(c[3])
                 : "r"(a[0]), "r"(a[1]), "r"(a[2]), "r"(a[3]),
                   "r"(b[0]), "r"(b[1]));
}
// MUFU exp2 (ex2.approx.f32)
__device__ __forceinline__ float exp2_mufu(float x) {
    float y;
    asm("ex2.approx.f32 %0, %1;" : "=f"(y) : "f"(x));
    return y;
}
// pack (v0,v1) -> f16x2 word (v0 in low half)
__device__ __forceinline__ uint32_t cvtf16x2(float v0, float v1) {
    uint32_t r;
    asm("cvt.rn.f16x2.f32 %0, %1, %2;" : "=r"(r) : "f"(v1), "f"(v0));
    return r;
}
// split (v0,v1) f32 pair -> f16x2 hi word + f16x2 residual word (22-bit total)
__device__ __forceinline__ void splitpack16(float v0, float v1, uint32_t& h, uint32_t& l) {
    h = cvtf16x2(v0, v1);
    __half2 hh = *reinterpret_cast<__half2*>(&h);
    float2 f = __half22float2(hh);
    l = cvtf16x2(v0 - f.x, v1 - f.y);
}

// ---------------------------------------------------------------------------
// conv_act: fp32 activations -> hi/lo fp16 (GEMM inputs)
// ---------------------------------------------------------------------------
__global__ void __launch_bounds__(256) conv_act(
    const float* __restrict__ x, __half* __restrict__ hi,
    __half* __restrict__ lo, int n4)
{
    int i = blockIdx.x * blockDim.x + threadIdx.x;
    if (i >= n4) return;
    float4 v = ((const float4*)x)[i];
    uint32_t h0, l0, h1, l1;
    splitpack16(v.x, v.y, h0, l0);
    splitpack16(v.z, v.w, h1, l1);
    ((uint2*)hi)[i] = make_uint2(h0, h1);
    ((uint2*)lo)[i] = make_uint2(l0, l1);
}

// W[k][n] fp32 -> W^T fp16 single [n][k]
__global__ void __launch_bounds__(256) conv_w(
    const float* __restrict__ W, __half* __restrict__ t16)
{
    __shared__ float t[32][33];
    const int n0 = blockIdx.x * 32, k0 = blockIdx.y * 32;
#pragma unroll
    for (int j = 0; j < 4; j++)
        t[threadIdx.y + j * 8][threadIdx.x] =
            W[(size_t)(k0 + threadIdx.y + j * 8) * DIM + n0 + threadIdx.x];
    __syncthreads();
#pragma unroll
    for (int j = 0; j < 4; j++) {
        float v = t[threadIdx.x][threadIdx.y + j * 8];
        size_t o = (size_t)(n0 + threadIdx.y + j * 8) * DIM + k0 + threadIdx.x;
        t16[o] = __float2half(v);
    }
}

// bool/int mask -> additive bf16 bias (-16384 masked, 0 allowed)
__global__ void __launch_bounds__(256) conv_mask(
    const int* __restrict__ m, __nv_bfloat16* __restrict__ mb, int n4)
{
    int i = blockIdx.x * blockDim.x + threadIdx.x;
    if (i >= n4) return;
    int4 v = ((const int4*)m)[i];
    const __nv_bfloat16 NEG = __float2bfloat16(-16384.0f);
    const __nv_bfloat16 ZER = __float2bfloat16(0.0f);
    __nv_bfloat162 a = __halves2bfloat162(v.x ? NEG : ZER, v.y ? NEG : ZER);
    __nv_bfloat162 b = __halves2bfloat162(v.z ? NEG : ZER, v.w ? NEG : ZER);
    ((__nv_bfloat162*)mb)[2 * i]     = a;
    ((__nv_bfloat162*)mb)[2 * i + 1] = b;
}

// ---------------------------------------------------------------------------
// mma.sync fp16x2 GEMM:  C = (Ah+Al) @ W16^T (+bias)*alpha   (2 MMA products)
// CTA tile 128x128, 8 warps (2x4), warp tile 64x32, k-step 32.
// A smem rows 128B: [hi 64B | lo 64B]. W smem rows 128B: [data 64B | dup 64B]
// (duplicate keeps the 8-chunk swizzle conflict-free; addressing == R10).
// 3-stage cp.async pipeline, ONE __syncthreads per k-step.
// Output: f32 (Cf) OR fp16 hi/lo split (Ch,Cl) OR fp16 single (Ch, Cl=null).
// ---------------------------------------------------------------------------
#define GSTAGE 32768               // A 16KB + W 16KB
#define GEMM_SMEM (3 * GSTAGE)     // 96KB, 2 CTAs/SM
#define NKSTEP (DIM / 32)          // 32

__device__ __forceinline__ void gemm_load_tile(
    uint32_t smb, const char* const* srcs, int kt, int s, int tid)
{
#pragma unroll
    for (int u = 0; u < 8; u++) {
        int idx  = u * 256 + tid;
        int tile = idx >> 10;
        int r    = (idx >> 3) & 127;
        int c    = idx & 7;
        // A: c<4 -> Ah chunks, c>=4 -> Al chunks.  W: c>=4 duplicates c-4.
        const char* src = srcs[tile * 2 + (c >> 2)]
                        + (size_t)r * 2048 + kt * 64 + (c & 3) * 16;
        uint32_t dst = smb + s * GSTAGE + tile * 16384
                     + r * 128 + ((c ^ (r & 7)) << 4);
        cpasync16(dst, src);
    }
}

__device__ __forceinline__ void gemm_compute_stage(
    uint32_t smb, int s, int lane, int warp_m, int warp_n, float acc[4][4][4])
{
    const uint32_t abase = smb + s * GSTAGE;
    const uint32_t wbase = abase + 16384;
    const int kh = lane >> 4;

#pragma unroll
    for (int kb = 0; kb < 2; kb++) {
        uint32_t a_h[4][4], a_l[4][4];
#pragma unroll
        for (int i = 0; i < 4; i++) {
            int rl = warp_m * 64 + i * 16 + (lane & 15);
            int ch0 = (kb * 2 + kh) ^ (rl & 7);
            int ch1 = (4 + kb * 2 + kh) ^ (rl & 7);
            ldsm4(a_h[i], abase + rl * 128 + (ch0 << 4));
            ldsm4(a_l[i], abase + rl * 128 + (ch1 << 4));
        }
        uint32_t b[4][2];
#pragma unroll
        for (int j2 = 0; j2 < 2; j2++) {
            int nl = warp_n * 32 + j2 * 16 + ((lane >> 3) & 1) * 8 + (lane & 7);
            int ch0 = (kb * 2 + kh) ^ (nl & 7);
            uint32_t t[4];
            ldsm4(t, wbase + nl * 128 + (ch0 << 4));
            b[j2 * 2][0]     = t[0]; b[j2 * 2][1]     = t[2];
            b[j2 * 2 + 1][0] = t[1]; b[j2 * 2 + 1][1] = t[3];
        }
#pragma unroll
        for (int i = 0; i < 4; i++)
#pragma unroll
            for (int jn = 0; jn < 4; jn++) {
                mma_f16(acc[i][jn], a_h[i], b[jn]);
                mma_f16(acc[i][jn], a_l[i], b[jn]);
            }
    }
}

__global__ void __launch_bounds__(256, 2) gemm_mma(
    const __half* __restrict__ Ah, const __half* __restrict__ Al,
    const __half* __restrict__ W16,
    const float* __restrict__ bias, float* __restrict__ Cf,
    __half* __restrict__ Ch, __half* __restrict__ Cl, float alpha)
{
    extern __shared__ char sm[];
    const int tid = threadIdx.x;
    const int lane = tid & 31, wid = tid >> 5;
    const int bx = blockIdx.x, by = blockIdx.y;
    const int warp_m = wid & 1, warp_n = wid >> 1;
    const uint32_t smb = (uint32_t)__cvta_generic_to_shared(sm);

    const char* srcs[4] = {
        (const char*)Ah + (size_t)by * 128 * 2048,
        (const char*)Al + (size_t)by * 128 * 2048,
        (const char*)W16 + (size_t)bx * 128 * 2048,
        (const char*)W16 + (size_t)bx * 128 * 2048
    };

    float acc[4][4][4];
#pragma unroll
    for (int i = 0; i < 4; i++)
#pragma unroll
        for (int j = 0; j < 4; j++)
#pragma unroll
            for (int r = 0; r < 4; r++) acc[i][j][r] = 0.f;

    gemm_load_tile(smb, srcs, 0, 0, tid);
    asm volatile("cp.async.commit_group;" ::: "memory");
    gemm_load_tile(smb, srcs, 1, 1, tid);
    asm volatile("cp.async.commit_group;" ::: "memory");

    int sc = 0, sl = 2;    // compute stage, load stage (3-stage ring)
#pragma unroll 1
    for (int kt = 0; kt < NKSTEP; kt++) {
        asm volatile("cp.async.wait_group 1;" ::: "memory");
        __syncthreads();
        if (kt + 2 < NKSTEP)
            gemm_load_tile(smb, srcs, kt + 2, sl, tid);
        asm volatile("cp.async.commit_group;" ::: "memory");
        gemm_compute_stage(smb, sc, lane, warp_m, warp_n, acc);
        sc = (sc == 2) ? 0 : sc + 1;
        sl = (sl == 2) ? 0 : sl + 1;
    }

    const int r0 = lane >> 2;
    const int c0 = (lane & 3) * 2;
#pragma unroll
    for (int jn = 0; jn < 4; jn++) {
        int col = bx * 128 + warp_n * 32 + jn * 8 + c0;
        float b0 = bias[col], b1 = bias[col + 1];
#pragma unroll
        for (int i = 0; i < 4; i++) {
            int row = by * 128 + warp_m * 64 + i * 16 + r0;
            float v0 = (acc[i][jn][0] + b0) * alpha;
            float v1 = (acc[i][jn][1] + b1) * alpha;
            float v2 = (acc[i][jn][2] + b0) * alpha;
            float v3 = (acc[i][jn][3] + b1) * alpha;
            if (Cf) {
                *(float2*)(Cf + (size_t)row * DIM + col)       = make_float2(v0, v1);
                *(float2*)(Cf + (size_t)(row + 8) * DIM + col) = make_float2(v2, v3);
            } else if (Cl) {
                uint32_t h, l;
                splitpack16(v0, v1, h, l);
                *(uint32_t*)(Ch + (size_t)row * DIM + col) = h;
                *(uint32_t*)(Cl + (size_t)row * DIM + col) = l;
                splitpack16(v2, v3, h, l);
                *(uint32_t*)(Ch + (size_t)(row + 8) * DIM + col) = h;
                *(uint32_t*)(Cl + (size_t)(row + 8) * DIM + col) = l;
            } else {   // fp16 single output (K / V projections)
                *(uint32_t*)(Ch + (size_t)row * DIM + col)       = cvtf16x2(v0, v1);
                *(uint32_t*)(Ch + (size_t)(row + 8) * DIM + col) = cvtf16x2(v2, v3);
            }
        }
    }
}

// ---------------------------------------------------------------------------
// Tensor-core flash attention. S = (Qh+Ql)·K16 (fp16x2); P·V in fp16.
// CTA: 128 q-rows x 1 head. 8 warps x 16 q-rows. 64-key tiles.
// 3-stage KV pipeline, ONE __syncthreads per tile.
// smem: Q 32KB | 3 x (K 8KB + V 8KB) = 48KB. Total 80KB.
// ---------------------------------------------------------------------------
#define KVSTAGE 16384
#define ATTN_SMEM (32768 + 3 * KVSTAGE)   // 81920
#define NTILE (SEQ / 64)                  // 32

__global__ void __launch_bounds__(256) attn_mma(
    const __half* __restrict__ qh, const __half* __restrict__ ql,
    const __half* __restrict__ k16, const __half* __restrict__ v16,
    const __nv_bfloat16* __restrict__ mb,
    __half* __restrict__ oh, __half* __restrict__ ol)
{
    extern __shared__ char sm[];
    const uint32_t smb = (uint32_t)__cvta_generic_to_shared(sm);
    const uint32_t QS = smb;
    const uint32_t KVS = smb + 32768;

    const int tid = threadIdx.x;
    const int lane = tid & 31, wid = tid >> 5;
    const int bx = blockIdx.x;        // q tile (of 128)
    const int hy = blockIdx.y;        // head
    const int bz = blockIdx.z;        // batch
    const int g = lane >> 2, t4 = lane & 3;

    const size_t qrow0 = (size_t)bz * SEQ + bx * 128;
    const size_t colofs = (size_t)hy * DPH;

    // ---- stage Q (hi|lo fp16), 8 cp.async per thread ----
#pragma unroll
    for (int u = 0; u < 8; u++) {
        int idx = u * 256 + tid;          // 0..2047
        int r  = idx & 127;
        int hl = (idx >> 7) & 1;
        int c  = idx >> 8;                // 0..7
        const __half* src = (hl ? ql : qh) + (qrow0 + r) * DIM + colofs + c * 8;
        cpasync16(QS + r * 256 + hl * 128 + ((c ^ (r & 7)) << 4), src);
    }
    asm volatile("cp.async.commit_group;" ::: "memory");

    // ---- KV tile loader: K fp16 (512 cp16) + V fp16 (512 cp16) ----
#define LOAD_KV(tt, s) do {                                                    \
    int k0_ = (tt) * 64;                                                       \
    _Pragma("unroll")                                                          \
    for (int u = 0; u < 4; u++) {                                              \
        int idx = u * 256 + tid;                                               \
        if (u < 2) {                                                           \
            int r = (idx >> 3) & 63, c = idx & 7;                              \
            const __half* src = k16                                            \
                + ((size_t)bz * SEQ + k0_ + r) * DIM + colofs + c * 8;         \
            cpasync16(KVS + (s) * KVSTAGE + r * 128                            \
                      + ((c ^ (r & 7)) << 4), src);                            \
        } else {                                                               \
            int j = idx - 512;                                                 \
            int r = j >> 3, c = j & 7;                                         \
            const __half* src = v16                                            \
                + ((size_t)bz * SEQ + k0_ + r) * DIM + colofs + c * 8;         \
            cpasync16(KVS + (s) * KVSTAGE + 8192 + r * 128                     \
                      + ((c ^ (r & 7)) << 4), src);                            \
        }                                                                      \
    }                                                                          \
} while (0)

    LOAD_KV(0, 0);
    asm volatile("cp.async.commit_group;" ::: "memory");
    LOAD_KV(1, 1);
    asm volatile("cp.async.commit_group;" ::: "memory");

    // Q done (2 most recent groups may pend), then pull Q fragments once.
    asm volatile("cp.async.wait_group 2;" ::: "memory");
    __syncthreads();

    uint32_t Qh[4][4], Ql[4][4];
    {
        int rl = wid * 16 + (lane & 15);
#pragma unroll
        for (int k = 0; k < 4; k++) {
            int ch = (2 * k + (lane >> 4)) ^ (rl & 7);
            uint32_t a = QS + rl * 256 + (ch << 4);
            ldsm4(Qh[k], a);
            ldsm4(Ql[k], a + 128);
        }
    }

    float O[8][4];
#pragma unroll
    for (int j = 0; j < 8; j++)
#pragma unroll
        for (int r = 0; r < 4; r++) O[j][r] = 0.f;
    float m_g = -1e30f, m_g8 = -1e30f, l_g = 0.f, l_g8 = 0.f;

    const __nv_bfloat16* brow_g  = mb + ((size_t)bz * SEQ + bx * 128 + wid * 16 + g) * SEQ + 2 * t4;
    const __nv_bfloat16* brow_g8 = brow_g + 8 * SEQ;

    int sc = 0, sl = 2;    // compute stage, load stage (3-stage ring)
#pragma unroll 1
    for (int t = 0; t < NTILE; t++) {
        asm volatile("cp.async.wait_group 1;" ::: "memory");
        __syncthreads();
        if (t + 2 < NTILE) LOAD_KV(t + 2, sl);
        asm volatile("cp.async.commit_group;" ::: "memory");
        const uint32_t stg = KVS + sc * KVSTAGE;

        // ---- C init from additive mask bias ----
        float C[8][4];
#pragma unroll
        for (int j = 0; j < 8; j++) {
            __nv_bfloat162 b0 = *(const __nv_bfloat162*)(brow_g  + t * 64 + j * 8);
            __nv_bfloat162 b1 = *(const __nv_bfloat162*)(brow_g8 + t * 64 + j * 8);
            float2 f0 = __bfloat1622float2(b0);
            float2 f1 = __bfloat1622float2(b1);
            C[j][0] = f0.x; C[j][1] = f0.y;
            C[j][2] = f1.x; C[j][3] = f1.y;
        }

        // ---- S = (Qh+Ql) K^T (fp16x2), K rows 128B ----
        {
            int krl = ((lane >> 3) & 1) * 8 + (lane & 7);
#pragma unroll
            for (int j2 = 0; j2 < 4; j2++) {
                int rr = j2 * 16 + krl;
#pragma unroll
                for (int k = 0; k < 4; k++) {
                    int ch = (2 * k + (lane >> 4)) ^ (rr & 7);
                    uint32_t th[4];
                    ldsm4(th, stg + rr * 128 + (ch << 4));
                    uint32_t bh0[2] = { th[0], th[2] }, bh1[2] = { th[1], th[3] };
                    mma_f16(C[2 * j2],     Qh[k], bh0);
                    mma_f16(C[2 * j2],     Ql[k], bh0);
                    mma_f16(C[2 * j2 + 1], Qh[k], bh1);
                    mma_f16(C[2 * j2 + 1], Ql[k], bh1);
                }
            }
        }

        // ---- online softmax (base 2; Q pre-scaled by log2 e) ----
        float mx0 = -1e30f, mx1 = -1e30f;
#pragma unroll
        for (int j = 0; j < 8; j++) {
            mx0 = fmaxf(mx0, fmaxf(C[j][0], C[j][1]));
            mx1 = fmaxf(mx1, fmaxf(C[j][2], C[j][3]));
        }
        mx0 = fmaxf(mx0, __shfl_xor_sync(0xffffffffu, mx0, 1));
        mx0 = fmaxf(mx0, __shfl_xor_sync(0xffffffffu, mx0, 2));
        mx1 = fmaxf(mx1, __shfl_xor_sync(0xffffffffu, mx1, 1));
        mx1 = fmaxf(mx1, __shfl_xor_sync(0xffffffffu, mx1, 2));
        float mn0 = fmaxf(m_g, mx0), mn1 = fmaxf(m_g8, mx1);
        float cg = exp2_mufu(m_g - mn0), cg8 = exp2_mufu(m_g8 - mn1);
        m_g = mn0; m_g8 = mn1;

        float s0 = 0.f, s1 = 0.f;
#pragma unroll
        for (int j = 0; j < 8; j++) {
            C[j][0] = exp2_mufu(C[j][0] - mn0);
            C[j][1] = exp2_mufu(C[j][1] - mn0);
            C[j][2] = exp2_mufu(C[j][2] - mn1);
            C[j][3] = exp2_mufu(C[j][3] - mn1);
            s0 += C[j][0] + C[j][1];
            s1 += C[j][2] + C[j][3];
        }
        l_g  = l_g  * cg  + s0;
        l_g8 = l_g8 * cg8 + s1;
#pragma unroll
        for (int j = 0; j < 8; j++) {
            O[j][0] *= cg;  O[j][1] *= cg;
            O[j][2] *= cg8; O[j][3] *= cg8;
        }

        // ---- pack P -> fp16 A-fragments ----
        uint32_t Pf[4][4];
#pragma unroll
        for (int k = 0; k < 4; k++)
#pragma unroll
            for (int rr = 0; rr < 4; rr++) {
                int j = 2 * k + (rr >> 1);
                int e = (rr & 1) * 2;
                Pf[k][rr] = cvtf16x2(C[j][e], C[j][e + 1]);
            }

        // ---- O += P V (fp16), V via ldmatrix.trans ----
        const uint32_t vstg = stg + 8192;
#pragma unroll
        for (int jd = 0; jd < 8; jd++) {
            uint32_t a0 = vstg + lane * 128 + ((jd ^ (lane & 7)) << 4);
            uint32_t a1 = vstg + (lane + 32) * 128 + ((jd ^ (lane & 7)) << 4);
            uint32_t tv0[4], tv1[4];
            ldsm4t(tv0, a0);
            ldsm4t(tv1, a1);
            uint32_t Vf[4][2] = { {tv0[0],tv0[1]}, {tv0[2],tv0[3]},
                                  {tv1[0],tv1[1]}, {tv1[2],tv1[3]} };
#pragma unroll
            for (int k = 0; k < 4; k++)
                mma_f16(O[jd], Pf[k], Vf[k]);
        }

        sc = (sc == 2) ? 0 : sc + 1;
        sl = (sl == 2) ? 0 : sl + 1;
    }

    // ---- epilogue: normalize, split to fp16 hi/lo, store ----
    l_g  += __shfl_xor_sync(0xffffffffu, l_g, 1);
    l_g  += __shfl_xor_sync(0xffffffffu, l_g, 2);
    l_g8 += __shfl_xor_sync(0xffffffffu, l_g8, 1);
    l_g8 += __shfl_xor_sync(0xffffffffu, l_g8, 2);
    float ig = 1.f / l_g, ig8 = 1.f / l_g8;

    size_t row_g  = qrow0 + wid * 16 + g;
    size_t off_g  = row_g * DIM + colofs + 2 * t4;
    size_t off_g8 = off_g + 8 * DIM;
#pragma unroll
    for (int jd = 0; jd < 8; jd++) {
        uint32_t h, l;
        splitpack16(O[jd][0] * ig, O[jd][1] * ig, h, l);
        *(uint32_t*)(oh + off_g + jd * 8) = h;
        *(uint32_t*)(ol + off_g + jd * 8) = l;
        splitpack16(O[jd][2] * ig8, O[jd][3] * ig8, h, l);
        *(uint32_t*)(oh + off_g8 + jd * 8) = h;
        *(uint32_t*)(ol + off_g8 + jd * 8) = l;
    }
#undef LOAD_KV
}

// ---------------------------------------------------------------------------
extern "C" void kernel_launch(void* const* d_in, const int* in_sizes, int n_in,
                              void* d_out, int out_size)
{
    (void)in_sizes; (void)n_in; (void)out_size;
    const float* key   = (const float*)d_in[0];
    const float* value = (const float*)d_in[1];
    const float* query = (const float*)d_in[2];
    const int*   mask  = (const int*)  d_in[3];
    const float* Wq = (const float*)d_in[4];
    const float* bq = (const float*)d_in[5];
    const float* Wk = (const float*)d_in[6];
    const float* bk = (const float*)d_in[7];
    const float* Wv = (const float*)d_in[8];
    const float* bv = (const float*)d_in[9];
    const float* Wo = (const float*)d_in[10];
    const float* bo = (const float*)d_in[11];
    float* out = (float*)d_out;

    __half *gah, *gal, *gw16, *gqh, *gql, *gk16, *gv16;
    __nv_bfloat16 *gmb;
    cudaGetSymbolAddress((void**)&gah, g_ah);
    cudaGetSymbolAddress((void**)&gal, g_al);
    cudaGetSymbolAddress((void**)&gw16, g_w16);
    cudaGetSymbolAddress((void**)&gqh, g_qh);
    cudaGetSymbolAddress((void**)&gql, g_ql);
    cudaGetSymbolAddress((void**)&gk16, g_k16);
    cudaGetSymbolAddress((void**)&gv16, g_v16);
    cudaGetSymbolAddress((void**)&gmb, g_mb);

    cudaFuncSetAttribute(gemm_mma,
                         cudaFuncAttributeMaxDynamicSharedMemorySize, GEMM_SMEM);
    cudaFuncSetAttribute(attn_mma,
                         cudaFuncAttributeMaxDynamicSharedMemorySize, ATTN_SMEM);

    const dim3 ggrid(DIM / 128, MROWS / 128);       // (8, 32) = 256 CTAs
    const dim3 wgrid(32, 32);
    const dim3 wblk(32, 8);
    const int n4 = MROWS * DIM / 4;
    const int nm4 = BATCH * SEQ * SEQ / 4;

    // mask -> additive bias
    conv_mask<<<nm4 / 256, 256>>>(mask, gmb, nm4);

    // Q projection: fold 1/sqrt(DPH) * log2(e); fp16 split output
    const float alpha_q = 0.125f * 1.4426950408889634f;
    conv_w<<<wgrid, wblk>>>(Wq, gw16);
    conv_act<<<n4 / 256, 256>>>(query, gah, gal, n4);
    gemm_mma<<<ggrid, 256, GEMM_SMEM>>>(gah, gal, gw16, bq, nullptr, gqh, gql, alpha_q);

    // K projection -> fp16 single
    conv_w<<<wgrid, wblk>>>(Wk, gw16);
    conv_act<<<n4 / 256, 256>>>(key, gah, gal, n4);
    gemm_mma<<<ggrid, 256, GEMM_SMEM>>>(gah, gal, gw16, bk, nullptr, gk16, nullptr, 1.0f);

    // V projection -> fp16 single
    conv_w<<<wgrid, wblk>>>(Wv, gw16);
    conv_act<<<n4 / 256, 256>>>(value, gah, gal, n4);
    gemm_mma<<<ggrid, 256, GEMM_SMEM>>>(gah, gal, gw16, bv, nullptr, gv16, nullptr, 1.0f);

    // Attention -> ctx fp16 split directly into out-projection inputs
    attn_mma<<<dim3(SEQ / 128, HEADS, BATCH), 256, ATTN_SMEM>>>(
        gqh, gql, gk16, gv16, gmb, gah, gal);

    // Output projection -> f32 out
    conv_w<<<wgrid, wblk>>>(Wo, gw16);
    gemm_mma<<<ggrid, 256, GEMM_SMEM>>>(gah, gal, gw16, bo, out, nullptr, nullptr, 1.0f);
}

// round 12
// speedup vs baseline: 4.6487x; 1.1379x over previous
#include <cuda_runtime.h>
#include <cuda_bf16.h>
#include <cuda_fp16.h>
#include <math.h>
#include <stdint.h>

// Problem constants (B=2, S=2048, D=1024, H=16, DPH=64)
#define BATCH 2
#define SEQ   2048
#define DIM   1024
#define HEADS 16
#define DPH   64
#define MROWS (BATCH * SEQ)   // 4096

// ---------------------------------------------------------------------------
// Scratch (allocation-free rule: __device__ globals; 16B-aligned for cp.async)
// ---------------------------------------------------------------------------
__device__ __align__(16) __half g_ah[MROWS * DIM];   // activation hi / ctx hi
__device__ __align__(16) __half g_al[MROWS * DIM];   // activation lo / ctx lo
__device__ __align__(16) __half g_w16[DIM * DIM];    // W^T fp16 single [n][k]
__device__ __align__(16) __half g_q16[MROWS * DIM];  // Q fp16 single
__device__ __align__(16) __half g_k16[MROWS * DIM];  // K fp16 single
__device__ __align__(16) __half g_v16[MROWS * DIM];  // V fp16 single
__device__ __align__(16) __nv_bfloat16 g_mb[(size_t)BATCH * SEQ * SEQ];  // mask bias

// ---------------------------------------------------------------------------
// Baseline-ISA PTX helpers
// ---------------------------------------------------------------------------
__device__ __forceinline__ void cpasync16(uint32_t dst, const void* src) {
    asm volatile("cp.async.cg.shared.global [%0], [%1], 16;"
                 :: "r"(dst), "l"(src) : "memory");
}
__device__ __forceinline__ void ldsm4(uint32_t* r, uint32_t addr) {
    asm volatile("ldmatrix.sync.aligned.m8n8.x4.shared.b16 {%0,%1,%2,%3}, [%4];"
                 : "=r"(r[0]), "=r"(r[1]), "=r"(r[2]), "=r"(r[3]) : "r"(addr));
}
__device__ __forceinline__ void ldsm4t(uint32_t* r, uint32_t addr) {
    asm volatile("ldmatrix.sync.aligned.m8n8.x4.trans.shared.b16 {%0,%1,%2,%3}, [%4];"
                 : "=r"(r[0]), "=r"(r[1]), "=r"(r[2]), "=r"(r[3]) : "r"(addr));
}
__device__ __forceinline__ void mma_f16(float* c, const uint32_t* a, const uint32_t* b) {
    asm volatile("mma.sync.aligned.m16n8k16.row.col.f32.f16.f16.f32 "
                 "{%0,%1,%2,%3}, {%4,%5,%6,%7}, {%8,%9}, {%0,%1,%2,%3};"
                 : "+f"(c[0]), "+f"(c[1]), "+f"(c[2]), "+f"(c[3])
                 : "r"(a[0]), "r"(a[1]), "r"(a[2]), "r"(a[3]),
                   "r"(b[0]), "r"(b[1]));
}
// MUFU exp2 (ex2.approx.f32)
__device__ __forceinline__ float exp2_mufu(float x) {
    float y;
    asm("ex2.approx.f32 %0, %1;" : "=f"(y) : "f"(x));
    return y;
}
// pack (v0,v1) -> f16x2 word (v0 in low half)
__device__ __forceinline__ uint32_t cvtf16x2(float v0, float v1) {
    uint32_t r;
    asm("cvt.rn.f16x2.f32 %0, %1, %2;" : "=r"(r) : "f"(v1), "f"(v0));
    return r;
}
// split (v0,v1) f32 pair -> f16x2 hi word + f16x2 residual word (22-bit total)
__device__ __forceinline__ void splitpack16(float v0, float v1, uint32_t& h, uint32_t& l) {
    h = cvtf16x2(v0, v1);
    __half2 hh = *reinterpret_cast<__half2*>(&h);
    float2 f = __half22float2(hh);
    l = cvtf16x2(v0 - f.x, v1 - f.y);
}

// ---------------------------------------------------------------------------
// conv_act: fp32 activations -> hi/lo fp16 (GEMM inputs)
// ---------------------------------------------------------------------------
__global__ void __launch_bounds__(256) conv_act(
    const float* __restrict__ x, __half* __restrict__ hi,
    __half* __restrict__ lo, int n4)
{
    int i = blockIdx.x * blockDim.x + threadIdx.x;
    if (i >= n4) return;
    float4 v = ((const float4*)x)[i];
    uint32_t h0, l0, h1, l1;
    splitpack16(v.x, v.y, h0, l0);
    splitpack16(v.z, v.w, h1, l1);
    ((uint2*)hi)[i] = make_uint2(h0, h1);
    ((uint2*)lo)[i] = make_uint2(l0, l1);
}

// W[k][n] fp32 -> W^T fp16 single [n][k]
__global__ void __launch_bounds__(256) conv_w(
    const float* __restrict__ W, __half* __restrict__ t16)
{
    __shared__ float t[32][33];
    const int n0 = blockIdx.x * 32, k0 = blockIdx.y * 32;
#pragma unroll
    for (int j = 0; j < 4; j++)
        t[threadIdx.y + j * 8][threadIdx.x] =
            W[(size_t)(k0 + threadIdx.y + j * 8) * DIM + n0 + threadIdx.x];
    __syncthreads();
#pragma unroll
    for (int j = 0; j < 4; j++) {
        float v = t[threadIdx.x][threadIdx.y + j * 8];
        size_t o = (size_t)(n0 + threadIdx.y + j * 8) * DIM + k0 + threadIdx.x;
        t16[o] = __float2half(v);
    }
}

// bool/int mask -> additive bf16 bias (-16384 masked, 0 allowed)
__global__ void __launch_bounds__(256) conv_mask(
    const int* __restrict__ m, __nv_bfloat16* __restrict__ mb, int n4)
{
    int i = blockIdx.x * blockDim.x + threadIdx.x;
    if (i >= n4) return;
    int4 v = ((const int4*)m)[i];
    const __nv_bfloat16 NEG = __float2bfloat16(-16384.0f);
    const __nv_bfloat16 ZER = __float2bfloat16(0.0f);
    __nv_bfloat162 a = __halves2bfloat162(v.x ? NEG : ZER, v.y ? NEG : ZER);
    __nv_bfloat162 b = __halves2bfloat162(v.z ? NEG : ZER, v.w ? NEG : ZER);
    ((__nv_bfloat162*)mb)[2 * i]     = a;
    ((__nv_bfloat162*)mb)[2 * i + 1] = b;
}

// ---------------------------------------------------------------------------
// mma.sync fp16x2 GEMM:  C = (Ah+Al) @ W16^T (+bias)*alpha   (2 MMA products)
// CTA tile 128x128, 8 warps (2x4), warp tile 64x32, k-step 64.
// Stage (48KB): Ah block 16KB | Al block 16KB | W block 16KB (no duplication).
// 2-stage cp.async pipeline. Output: f32 / fp16-split / fp16-single.
// ---------------------------------------------------------------------------
#define GSTAGE 49152               // 3 x 16KB blocks
#define GEMM_SMEM (2 * GSTAGE)     // 96KB, 2 CTAs/SM
#define NKSTEP (DIM / 64)          // 16

__device__ __forceinline__ void gemm_load_tile(
    uint32_t smb, const char* const* srcs, int kt, int s, int tid)
{
#pragma unroll
    for (int u = 0; u < 12; u++) {
        int idx   = u * 256 + tid;      // 0..3071
        int block = idx >> 10;          // 0=Ah, 1=Al, 2=W
        int j     = idx & 1023;
        int r     = j >> 3;             // 0..127
        int c     = j & 7;              // 16B chunk in 128B row
        const char* src = srcs[block] + (size_t)r * 2048 + kt * 128 + c * 16;
        uint32_t dst = smb + s * GSTAGE + block * 16384
                     + r * 128 + ((c ^ (r & 7)) << 4);
        cpasync16(dst, src);
    }
}

__device__ __forceinline__ void gemm_compute_stage(
    uint32_t smb, int s, int lane, int warp_m, int warp_n, float acc[4][4][4])
{
    const uint32_t abase = smb + s * GSTAGE;
    const uint32_t wbase = abase + 32768;
    const int kh = lane >> 4;

#pragma unroll
    for (int kb = 0; kb < 4; kb++) {
        uint32_t a_h[4][4], a_l[4][4];
#pragma unroll
        for (int i = 0; i < 4; i++) {
            int rl = warp_m * 64 + i * 16 + (lane & 15);
            int ch = (kb * 2 + kh) ^ (rl & 7);
            ldsm4(a_h[i], abase + rl * 128 + (ch << 4));
            ldsm4(a_l[i], abase + 16384 + rl * 128 + (ch << 4));
        }
        uint32_t b[4][2];
#pragma unroll
        for (int j2 = 0; j2 < 2; j2++) {
            int nl = warp_n * 32 + j2 * 16 + ((lane >> 3) & 1) * 8 + (lane & 7);
            int ch = (kb * 2 + kh) ^ (nl & 7);
            uint32_t t[4];
            ldsm4(t, wbase + nl * 128 + (ch << 4));
            b[j2 * 2][0]     = t[0]; b[j2 * 2][1]     = t[2];
            b[j2 * 2 + 1][0] = t[1]; b[j2 * 2 + 1][1] = t[3];
        }
#pragma unroll
        for (int i = 0; i < 4; i++)
#pragma unroll
            for (int jn = 0; jn < 4; jn++) {
                mma_f16(acc[i][jn], a_h[i], b[jn]);
                mma_f16(acc[i][jn], a_l[i], b[jn]);
            }
    }
}

__global__ void __launch_bounds__(256, 2) gemm_mma(
    const __half* __restrict__ Ah, const __half* __restrict__ Al,
    const __half* __restrict__ W16,
    const float* __restrict__ bias, float* __restrict__ Cf,
    __half* __restrict__ Ch, __half* __restrict__ Cl, float alpha)
{
    extern __shared__ char sm[];
    const int tid = threadIdx.x;
    const int lane = tid & 31, wid = tid >> 5;
    const int bx = blockIdx.x, by = blockIdx.y;
    const int warp_m = wid & 1, warp_n = wid >> 1;
    const uint32_t smb = (uint32_t)__cvta_generic_to_shared(sm);

    const char* srcs[3] = {
        (const char*)Ah + (size_t)by * 128 * 2048,
        (const char*)Al + (size_t)by * 128 * 2048,
        (const char*)W16 + (size_t)bx * 128 * 2048
    };

    float acc[4][4][4];
#pragma unroll
    for (int i = 0; i < 4; i++)
#pragma unroll
        for (int j = 0; j < 4; j++)
#pragma unroll
            for (int r = 0; r < 4; r++) acc[i][j][r] = 0.f;

    gemm_load_tile(smb, srcs, 0, 0, tid);
    asm volatile("cp.async.commit_group;" ::: "memory");
    gemm_load_tile(smb, srcs, 1, 1, tid);
    asm volatile("cp.async.commit_group;" ::: "memory");

#pragma unroll 1
    for (int kt = 0; kt < NKSTEP; kt++) {
        asm volatile("cp.async.wait_group 1;" ::: "memory");
        __syncthreads();
        gemm_compute_stage(smb, kt & 1, lane, warp_m, warp_n, acc);
        __syncthreads();
        if (kt + 2 < NKSTEP)
            gemm_load_tile(smb, srcs, kt + 2, kt & 1, tid);
        asm volatile("cp.async.commit_group;" ::: "memory");
    }

    const int r0 = lane >> 2;
    const int c0 = (lane & 3) * 2;
#pragma unroll
    for (int jn = 0; jn < 4; jn++) {
        int col = bx * 128 + warp_n * 32 + jn * 8 + c0;
        float b0 = bias[col], b1 = bias[col + 1];
#pragma unroll
        for (int i = 0; i < 4; i++) {
            int row = by * 128 + warp_m * 64 + i * 16 + r0;
            float v0 = (acc[i][jn][0] + b0) * alpha;
            float v1 = (acc[i][jn][1] + b1) * alpha;
            float v2 = (acc[i][jn][2] + b0) * alpha;
            float v3 = (acc[i][jn][3] + b1) * alpha;
            if (Cf) {
                *(float2*)(Cf + (size_t)row * DIM + col)       = make_float2(v0, v1);
                *(float2*)(Cf + (size_t)(row + 8) * DIM + col) = make_float2(v2, v3);
            } else if (Cl) {
                uint32_t h, l;
                splitpack16(v0, v1, h, l);
                *(uint32_t*)(Ch + (size_t)row * DIM + col) = h;
                *(uint32_t*)(Cl + (size_t)row * DIM + col) = l;
                splitpack16(v2, v3, h, l);
                *(uint32_t*)(Ch + (size_t)(row + 8) * DIM + col) = h;
                *(uint32_t*)(Cl + (size_t)(row + 8) * DIM + col) = l;
            } else {   // fp16 single output (Q / K / V projections)
                *(uint32_t*)(Ch + (size_t)row * DIM + col)       = cvtf16x2(v0, v1);
                *(uint32_t*)(Ch + (size_t)(row + 8) * DIM + col) = cvtf16x2(v2, v3);
            }
        }
    }
}

// ---------------------------------------------------------------------------
// Tensor-core flash attention. S = Q16·K16 (fp16 single); P·V in fp16.
// CTA: 128 q-rows x 1 head. 8 warps x 16 q-rows. 64-key tiles.
// 3-stage KV pipeline, ONE __syncthreads per tile.
// smem: Q 16KB | 3 x (K 8KB + V 8KB) = 48KB. Total 64KB.
// ---------------------------------------------------------------------------
#define KVSTAGE 16384
#define ATTN_SMEM (16384 + 3 * KVSTAGE)   // 65536
#define NTILE (SEQ / 64)                  // 32

__global__ void __launch_bounds__(256) attn_mma(
    const __half* __restrict__ q16,
    const __half* __restrict__ k16, const __half* __restrict__ v16,
    const __nv_bfloat16* __restrict__ mb,
    __half* __restrict__ oh, __half* __restrict__ ol)
{
    extern __shared__ char sm[];
    const uint32_t smb = (uint32_t)__cvta_generic_to_shared(sm);
    const uint32_t QS = smb;
    const uint32_t KVS = smb + 16384;

    const int tid = threadIdx.x;
    const int lane = tid & 31, wid = tid >> 5;
    const int bx = blockIdx.x;        // q tile (of 128)
    const int hy = blockIdx.y;        // head
    const int bz = blockIdx.z;        // batch
    const int g = lane >> 2, t4 = lane & 3;

    const size_t qrow0 = (size_t)bz * SEQ + bx * 128;
    const size_t colofs = (size_t)hy * DPH;

    // ---- stage Q (fp16 single), 4 cp.async per thread ----
#pragma unroll
    for (int u = 0; u < 4; u++) {
        int idx = u * 256 + tid;          // 0..1023
        int r = idx >> 3, c = idx & 7;
        const __half* src = q16 + (qrow0 + r) * DIM + colofs + c * 8;
        cpasync16(QS + r * 128 + ((c ^ (r & 7)) << 4), src);
    }
    asm volatile("cp.async.commit_group;" ::: "memory");

    // ---- KV tile loader: K fp16 (512 cp16) + V fp16 (512 cp16) ----
#define LOAD_KV(tt, s) do {                                                    \
    int k0_ = (tt) * 64;                                                       \
    _Pragma("unroll")                                                          \
    for (int u = 0; u < 4; u++) {                                              \
        int idx = u * 256 + tid;                                               \
        if (u < 2) {                                                           \
            int r = (idx >> 3) & 63, c = idx & 7;                              \
            const __half* src = k16                                            \
                + ((size_t)bz * SEQ + k0_ + r) * DIM + colofs + c * 8;         \
            cpasync16(KVS + (s) * KVSTAGE + r * 128                            \
                      + ((c ^ (r & 7)) << 4), src);                            \
        } else {                                                               \
            int j = idx - 512;                                                 \
            int r = j >> 3, c = j & 7;                                         \
            const __half* src = v16                                            \
                + ((size_t)bz * SEQ + k0_ + r) * DIM + colofs + c * 8;         \
            cpasync16(KVS + (s) * KVSTAGE + 8192 + r * 128                     \
                      + ((c ^ (r & 7)) << 4), src);                            \
        }                                                                      \
    }                                                                          \
} while (0)

    LOAD_KV(0, 0);
    asm volatile("cp.async.commit_group;" ::: "memory");
    LOAD_KV(1, 1);
    asm volatile("cp.async.commit_group;" ::: "memory");

    // Q done (2 most recent groups may pend), then pull Q fragments once.
    asm volatile("cp.async.wait_group 2;" ::: "memory");
    __syncthreads();

    uint32_t Qh[4][4];
    {
        int rl = wid * 16 + (lane & 15);
#pragma unroll
        for (int k = 0; k < 4; k++) {
            int ch = (2 * k + (lane >> 4)) ^ (rl & 7);
            ldsm4(Qh[k], QS + rl * 128 + (ch << 4));
        }
    }

    float O[8][4];
#pragma unroll
    for (int j = 0; j < 8; j++)
#pragma unroll
        for (int r = 0; r < 4; r++) O[j][r] = 0.f;
    float m_g = -1e30f, m_g8 = -1e30f, l_g = 0.f, l_g8 = 0.f;

    const __nv_bfloat16* brow_g  = mb + ((size_t)bz * SEQ + bx * 128 + wid * 16 + g) * SEQ + 2 * t4;
    const __nv_bfloat16* brow_g8 = brow_g + 8 * SEQ;

    int sc = 0, sl = 2;    // compute stage, load stage (3-stage ring)
#pragma unroll 1
    for (int t = 0; t < NTILE; t++) {
        asm volatile("cp.async.wait_group 1;" ::: "memory");
        __syncthreads();
        if (t + 2 < NTILE) LOAD_KV(t + 2, sl);
        asm volatile("cp.async.commit_group;" ::: "memory");
        const uint32_t stg = KVS + sc * KVSTAGE;

        // ---- C init from additive mask bias ----
        float C[8][4];
#pragma unroll
        for (int j = 0; j < 8; j++) {
            __nv_bfloat162 b0 = *(const __nv_bfloat162*)(brow_g  + t * 64 + j * 8);
            __nv_bfloat162 b1 = *(const __nv_bfloat162*)(brow_g8 + t * 64 + j * 8);
            float2 f0 = __bfloat1622float2(b0);
            float2 f1 = __bfloat1622float2(b1);
            C[j][0] = f0.x; C[j][1] = f0.y;
            C[j][2] = f1.x; C[j][3] = f1.y;
        }

        // ---- S = Q K^T (fp16 single) ----
        {
            int krl = ((lane >> 3) & 1) * 8 + (lane & 7);
#pragma unroll
            for (int j2 = 0; j2 < 4; j2++) {
                int rr = j2 * 16 + krl;
#pragma unroll
                for (int k = 0; k < 4; k++) {
                    int ch = (2 * k + (lane >> 4)) ^ (rr & 7);
                    uint32_t th[4];
                    ldsm4(th, stg + rr * 128 + (ch << 4));
                    uint32_t bh0[2] = { th[0], th[2] }, bh1[2] = { th[1], th[3] };
                    mma_f16(C[2 * j2],     Qh[k], bh0);
                    mma_f16(C[2 * j2 + 1], Qh[k], bh1);
                }
            }
        }

        // ---- online softmax (base 2; Q pre-scaled by log2 e) ----
        float mx0 = -1e30f, mx1 = -1e30f;
#pragma unroll
        for (int j = 0; j < 8; j++) {
            mx0 = fmaxf(mx0, fmaxf(C[j][0], C[j][1]));
            mx1 = fmaxf(mx1, fmaxf(C[j][2], C[j][3]));
        }
        mx0 = fmaxf(mx0, __shfl_xor_sync(0xffffffffu, mx0, 1));
        mx0 = fmaxf(mx0, __shfl_xor_sync(0xffffffffu, mx0, 2));
        mx1 = fmaxf(mx1, __shfl_xor_sync(0xffffffffu, mx1, 1));
        mx1 = fmaxf(mx1, __shfl_xor_sync(0xffffffffu, mx1, 2));
        float mn0 = fmaxf(m_g, mx0), mn1 = fmaxf(m_g8, mx1);
        float cg = exp2_mufu(m_g - mn0), cg8 = exp2_mufu(m_g8 - mn1);
        m_g = mn0; m_g8 = mn1;

        float s0 = 0.f, s1 = 0.f;
#pragma unroll
        for (int j = 0; j < 8; j++) {
            C[j][0] = exp2_mufu(C[j][0] - mn0);
            C[j][1] = exp2_mufu(C[j][1] - mn0);
            C[j][2] = exp2_mufu(C[j][2] - mn1);
            C[j][3] = exp2_mufu(C[j][3] - mn1);
            s0 += C[j][0] + C[j][1];
            s1 += C[j][2] + C[j][3];
        }
        l_g  = l_g  * cg  + s0;
        l_g8 = l_g8 * cg8 + s1;
#pragma unroll
        for (int j = 0; j < 8; j++) {
            O[j][0] *= cg;  O[j][1] *= cg;
            O[j][2] *= cg8; O[j][3] *= cg8;
        }

        // ---- pack P -> fp16 A-fragments ----
        uint32_t Pf[4][4];
#pragma unroll
        for (int k = 0; k < 4; k++)
#pragma unroll
            for (int rr = 0; rr < 4; rr++) {
                int j = 2 * k + (rr >> 1);
                int e = (rr & 1) * 2;
                Pf[k][rr] = cvtf16x2(C[j][e], C[j][e + 1]);
            }

        // ---- O += P V (fp16), V via ldmatrix.trans ----
        const uint32_t vstg = stg + 8192;
#pragma unroll
        for (int jd = 0; jd < 8; jd++) {
            uint32_t a0 = vstg + lane * 128 + ((jd ^ (lane & 7)) << 4);
            uint32_t a1 = vstg + (lane + 32) * 128 + ((jd ^ (lane & 7)) << 4);
            uint32_t tv0[4], tv1[4];
            ldsm4t(tv0, a0);
            ldsm4t(tv1, a1);
            uint32_t Vf[4][2] = { {tv0[0],tv0[1]}, {tv0[2],tv0[3]},
                                  {tv1[0],tv1[1]}, {tv1[2],tv1[3]} };
#pragma unroll
            for (int k = 0; k < 4; k++)
                mma_f16(O[jd], Pf[k], Vf[k]);
        }

        sc = (sc == 2) ? 0 : sc + 1;
        sl = (sl == 2) ? 0 : sl + 1;
    }

    // ---- epilogue: normalize, split to fp16 hi/lo, store ----
    l_g  += __shfl_xor_sync(0xffffffffu, l_g, 1);
    l_g  += __shfl_xor_sync(0xffffffffu, l_g, 2);
    l_g8 += __shfl_xor_sync(0xffffffffu, l_g8, 1);
    l_g8 += __shfl_xor_sync(0xffffffffu, l_g8, 2);
    float ig = 1.f / l_g, ig8 = 1.f / l_g8;

    size_t row_g  = qrow0 + wid * 16 + g;
    size_t off_g  = row_g * DIM + colofs + 2 * t4;
    size_t off_g8 = off_g + 8 * DIM;
#pragma unroll
    for (int jd = 0; jd < 8; jd++) {
        uint32_t h, l;
        splitpack16(O[jd][0] * ig, O[jd][1] * ig, h, l);
        *(uint32_t*)(oh + off_g + jd * 8) = h;
        *(uint32_t*)(ol + off_g + jd * 8) = l;
        splitpack16(O[jd][2] * ig8, O[jd][3] * ig8, h, l);
        *(uint32_t*)(oh + off_g8 + jd * 8) = h;
        *(uint32_t*)(ol + off_g8 + jd * 8) = l;
    }
#undef LOAD_KV
}

// ---------------------------------------------------------------------------
extern "C" void kernel_launch(void* const* d_in, const int* in_sizes, int n_in,
                              void* d_out, int out_size)
{
    (void)in_sizes; (void)n_in; (void)out_size;
    const float* key   = (const float*)d_in[0];
    const float* value = (const float*)d_in[1];
    const float* query = (const float*)d_in[2];
    const int*   mask  = (const int*)  d_in[3];
    const float* Wq = (const float*)d_in[4];
    const float* bq = (const float*)d_in[5];
    const float* Wk = (const float*)d_in[6];
    const float* bk = (const float*)d_in[7];
    const float* Wv = (const float*)d_in[8];
    const float* bv = (const float*)d_in[9];
    const float* Wo = (const float*)d_in[10];
    const float* bo = (const float*)d_in[11];
    float* out = (float*)d_out;

    __half *gah, *gal, *gw16, *gq16, *gk16, *gv16;
    __nv_bfloat16 *gmb;
    cudaGetSymbolAddress((void**)&gah, g_ah);
    cudaGetSymbolAddress((void**)&gal, g_al);
    cudaGetSymbolAddress((void**)&gw16, g_w16);
    cudaGetSymbolAddress((void**)&gq16, g_q16);
    cudaGetSymbolAddress((void**)&gk16, g_k16);
    cudaGetSymbolAddress((void**)&gv16, g_v16);
    cudaGetSymbolAddress((void**)&gmb, g_mb);

    cudaFuncSetAttribute(gemm_mma,
                         cudaFuncAttributeMaxDynamicSharedMemorySize, GEMM_SMEM);
    cudaFuncSetAttribute(attn_mma,
                         cudaFuncAttributeMaxDynamicSharedMemorySize, ATTN_SMEM);

    const dim3 ggrid(DIM / 128, MROWS / 128);       // (8, 32) = 256 CTAs
    const dim3 wgrid(32, 32);
    const dim3 wblk(32, 8);
    const int n4 = MROWS * DIM / 4;
    const int nm4 = BATCH * SEQ * SEQ / 4;

    // mask -> additive bias
    conv_mask<<<nm4 / 256, 256>>>(mask, gmb, nm4);

    // Q projection: fold 1/sqrt(DPH) * log2(e); fp16 single output
    const float alpha_q = 0.125f * 1.4426950408889634f;
    conv_w<<<wgrid, wblk>>>(Wq, gw16);
    conv_act<<<n4 / 256, 256>>>(query, gah, gal, n4);
    gemm_mma<<<ggrid, 256, GEMM_SMEM>>>(gah, gal, gw16, bq, nullptr, gq16, nullptr, alpha_q);

    // K projection -> fp16 single
    conv_w<<<wgrid, wblk>>>(Wk, gw16);
    conv_act<<<n4 / 256, 256>>>(key, gah, gal, n4);
    gemm_mma<<<ggrid, 256, GEMM_SMEM>>>(gah, gal, gw16, bk, nullptr, gk16, nullptr, 1.0f);

    // V projection -> fp16 single
    conv_w<<<wgrid, wblk>>>(Wv, gw16);
    conv_act<<<n4 / 256, 256>>>(value, gah, gal, n4);
    gemm_mma<<<ggrid, 256, GEMM_SMEM>>>(gah, gal, gw16, bv, nullptr, gv16, nullptr, 1.0f);

    // Attention -> ctx fp16 split directly into out-projection inputs
    attn_mma<<<dim3(SEQ / 128, HEADS, BATCH), 256, ATTN_SMEM>>>(
        gq16, gk16, gv16, gmb, gah, gal);

    // Output projection -> f32 out
    conv_w<<<wgrid, wblk>>>(Wo, gw16);
    gemm_mma<<<ggrid, 256, GEMM_SMEM>>>(gah, gal, gw16, bo, out, nullptr, nullptr, 1.0f);
}